// round 13
// baseline (speedup 1.0000x reference)
#include <cuda_runtime.h>
#include <cuda_fp16.h>
#include <math.h>
#include <stdint.h>

#define QL 1024
#define NH 16
#define DH 64
#define DM 1024
#define DI 4096
#define RL 2048
#define M2 (QL*2)
#define MR (RL*2)
#define ATT_SCALE 0.125f
#define SSTR ((size_t)32*QL*QL)

__device__ __forceinline__ uint32_t smem_u32(const void* p) {
    uint32_t a;
    asm("{ .reg .u64 t; cvta.to.shared.u64 t, %1; cvt.u32.u64 %0, t; }" : "=r"(a) : "l"(p));
    return a;
}
__device__ __forceinline__ void cp16(uint32_t dst, const void* src) {
    asm volatile("cp.async.cg.shared.global [%0], [%1], 16;" :: "r"(dst), "l"(src));
}
__device__ __forceinline__ void cp_commit() { asm volatile("cp.async.commit_group;" ::: "memory"); }
__device__ __forceinline__ void ldsm4(uint32_t (&r)[4], uint32_t addr) {
    asm volatile("ldmatrix.sync.aligned.m8n8.x4.shared.b16 {%0,%1,%2,%3}, [%4];"
        : "=r"(r[0]), "=r"(r[1]), "=r"(r[2]), "=r"(r[3]) : "r"(addr));
}
__device__ __forceinline__ void mma16816(float (&d)[4], const uint32_t (&a)[4],
                                         uint32_t b0, uint32_t b1) {
    asm volatile("mma.sync.aligned.m16n8k16.row.col.f32.f16.f16.f32 "
        "{%0,%1,%2,%3},{%4,%5,%6,%7},{%8,%9},{%0,%1,%2,%3};"
        : "+f"(d[0]), "+f"(d[1]), "+f"(d[2]), "+f"(d[3])
        : "r"(a[0]), "r"(a[1]), "r"(a[2]), "r"(a[3]), "r"(b0), "r"(b1));
}

// ---------------- scratch ----------------
__device__ float g_v [M2*DM];
__device__ float g_ef[2*M2*NH*2];
__device__ float g_o [2*M2*DM];
__device__ float g_y [2*M2*DM];
__device__ float g_z [2*M2*DM];
__device__ float g_bkT [32*QL];
__device__ float g_bkrT[32*RL];
__device__ float g_S [2*SSTR];
__device__ __align__(256) __half g_diffb[(size_t)2*QL*QL];
__device__ __align__(256) __half g_hb[M2*DM], g_rb[MR*DM], g_gb[M2*DM];
__device__ __align__(256) __half g_wqT[DM*DM], g_wkT[DM*DM], g_wvT[DM*DM];
__device__ __align__(256) __half g_wrT[DM*DM], g_woC[DM*DM];
__device__ __align__(256) __half g_w1T[DM*DI], g_w2T[DI*DM];
__device__ __align__(256) __half g_q1h[32*QL*DH], g_q2h[32*QL*DH];
__device__ __align__(256) __half g_khh[32*QL*DH];
__device__ __align__(256) __half g_krh[32*RL*DH];
__device__ __align__(256) __half g_vth[32*DH*QL];
__device__ __align__(256) __half g_Ph [2*SSTR];
__device__ __align__(256) __half g_at [2*M2*DM];
__device__ __align__(256) __half g_yh [2*M2*DM];
__device__ __align__(256) __half g_th [2*M2*DI];

// ---------------- small kernels ----------------
// z: 0 = h->hb, 1 = g->gb
__global__ void conv_hg(const float* __restrict__ H, const float* __restrict__ G,
                        __half* __restrict__ HB, __half* __restrict__ GB, int n4)
{
    int i = blockIdx.x * blockDim.x + threadIdx.x;
    if (i >= n4) return;
    const float* X = blockIdx.y ? G : H;
    __half* out = blockIdx.y ? GB : HB;
    float4 v = ((const float4*)X)[i];
    ((__half2*)out)[2*i]   = __halves2half2(__float2half_rn(v.x), __float2half_rn(v.y));
    ((__half2*)out)[2*i+1] = __halves2half2(__float2half_rn(v.z), __float2half_rn(v.w));
}

__global__ void conv_half(const float* __restrict__ X, __half* __restrict__ out, int n4)
{
    int i = blockIdx.x * blockDim.x + threadIdx.x;
    if (i >= n4) return;
    float4 v = ((const float4*)X)[i];
    ((__half2*)out)[2*i]   = __halves2half2(__float2half_rn(v.x), __float2half_rn(v.y));
    ((__half2*)out)[2*i+1] = __halves2half2(__float2half_rn(v.z), __float2half_rn(v.w));
}

// z selects among 4 DMxDM weights
__global__ void convT4_half(const float* __restrict__ W0, const float* __restrict__ W1,
                            const float* __restrict__ W2, const float* __restrict__ W3,
                            __half* __restrict__ O0, __half* __restrict__ O1,
                            __half* __restrict__ O2, __half* __restrict__ O3)
{
    __shared__ float t[32][33];
    const float* W = (blockIdx.z == 0) ? W0 : (blockIdx.z == 1) ? W1 : (blockIdx.z == 2) ? W2 : W3;
    __half* out    = (blockIdx.z == 0) ? O0 : (blockIdx.z == 1) ? O1 : (blockIdx.z == 2) ? O2 : O3;
    int k0 = blockIdx.y * 32, n0 = blockIdx.x * 32;
    int tx = threadIdx.x, ty = threadIdx.y;
#pragma unroll
    for (int p = 0; p < 4; p++)
        t[ty + p*8][tx] = W[(size_t)(k0 + ty + p*8)*DM + n0 + tx];
    __syncthreads();
#pragma unroll
    for (int p = 0; p < 4; p++)
        out[(size_t)(n0 + ty + p*8)*DM + k0 + tx] = __float2half_rn(t[tx][ty + p*8]);
}

__global__ void convT_half(const float* __restrict__ W, __half* __restrict__ out, int K, int N)
{
    __shared__ float t[32][33];
    int k0 = blockIdx.y * 32, n0 = blockIdx.x * 32;
    int tx = threadIdx.x, ty = threadIdx.y;
#pragma unroll
    for (int p = 0; p < 4; p++)
        t[ty + p*8][tx] = W[(size_t)(k0 + ty + p*8)*N + n0 + tx];
    __syncthreads();
#pragma unroll
    for (int p = 0; p < 4; p++)
        out[(size_t)(n0 + ty + p*8)*K + k0 + tx] = __float2half_rn(t[tx][ty + p*8]);
}

__global__ void repack_vT(const float* __restrict__ V, __half* __restrict__ out)
{
    __shared__ float tile[32][33];
    int j0 = blockIdx.x * 32, d0 = blockIdx.y * 32;
    int bn = blockIdx.z, b = bn >> 4, n = bn & 15;
    int tx = threadIdx.x, ty = threadIdx.y;
#pragma unroll
    for (int p = 0; p < 4; p++)
        tile[ty + p*8][tx] = V[((size_t)(j0 + ty + p*8)*2 + b)*DM + n*DH + d0 + tx];
    __syncthreads();
#pragma unroll
    for (int p = 0; p < 4; p++)
        out[((size_t)bn*DH + d0 + ty + p*8)*QL + j0 + tx] = __float2half_rn(tile[tx][ty + p*8]);
}

__global__ void prep_diff(const float* __restrict__ seg_mat, __half* __restrict__ diff)
{
    size_t idx = (size_t)blockIdx.x * blockDim.x + threadIdx.x;
    if (idx >= (size_t)2*QL*QL) return;
    int j = idx & 1023, i = (idx >> 10) & 1023, b = (int)(idx >> 20);
    diff[idx] = __float2half_rn(seg_mat[(((size_t)i*QL + j)*2 + b)*2 + 1]);
}

// out[bn][j] = sum_d bias[n*64+d] * X[bn][j][d]   (X fp16 head-major)
__global__ void bias_dotT_h(const __half* __restrict__ X, const float* __restrict__ bias,
                            float* __restrict__ outT, int total)
{
    const int gw = (blockIdx.x * blockDim.x + threadIdx.x) >> 5;
    const int lane = threadIdx.x & 31;
    if (gw >= total) return;
    const int n = (gw / (total >> 5)) & 15;   // total = 32*rows, rows pow2: bn = gw / rows
    // recompute cleanly: rows = total/32
    const int rows = total >> 5;
    const int bn = gw / rows;
    const int nn = bn & 15;
    (void)n;
    float s = bias[nn*DH + lane]      * __half2float(X[(size_t)gw*DH + lane])
            + bias[nn*DH + 32 + lane] * __half2float(X[(size_t)gw*DH + 32 + lane]);
#pragma unroll
    for (int o = 16; o; o >>= 1) s += __shfl_xor_sync(0xffffffffu, s, o);
    if (!lane) outT[gw] = s;
}

// ef from fp16 head-major q; y-dim selects stream
__global__ void ef_kernel_h(const __half* __restrict__ Q1, const __half* __restrict__ Q2,
                            const float* __restrict__ rsb, const float* __restrict__ se)
{
    const int gw = (blockIdx.x * blockDim.x + threadIdx.x) >> 5;
    const int lane = threadIdx.x & 31;
    if (gw >= M2 * NH) return;
    const __half* qh = blockIdx.y ? Q2 : Q1;
    float* ef = g_ef + (size_t)blockIdx.y * M2 * NH * 2;
    const int i = gw >> 5, b = (gw >> 4) & 1, n = gw & 15;
    const size_t qb = ((size_t)(b*16 + n)*QL + i)*DH;
    const float v0 = __half2float(qh[qb + lane])      + rsb[n*DH + lane];
    const float v1 = __half2float(qh[qb + 32 + lane]) + rsb[n*DH + 32 + lane];
    float s0 = v0*se[n*DH + lane] + v1*se[n*DH + 32 + lane];
    float s1 = v0*se[NH*DH + n*DH + lane] + v1*se[NH*DH + n*DH + 32 + lane];
#pragma unroll
    for (int o = 16; o; o >>= 1) {
        s0 += __shfl_xor_sync(0xffffffffu, s0, o);
        s1 += __shfl_xor_sync(0xffffffffu, s1, o);
    }
    if (!lane) { ef[gw*2] = s0; ef[gw*2 + 1] = s1; }
}

__global__ void vmean_fix(const float* __restrict__ V, __half* __restrict__ O)
{
    int bn = blockIdx.x, b = bn >> 4, n = bn & 15;
    int d = threadIdx.x;
    float s = 0.f;
    for (int j = 0; j < QL; j++) s += V[((size_t)j*2 + b)*DM + n*DH + d];
    s *= (1.0f/1024.0f);
    O[(size_t)M2*DM + (size_t)b*DM + n*DH + d] = __float2half_rn(s);
}

// ---------------- dense GEMM: 1-pass fp16, 3-stage, 2 CTA/SM ----------------
#define GSTAGE 32768
#define GSMEM_BYTES (3*GSTAGE)

__device__ __forceinline__ void g_load_stage(
    const __half* __restrict__ A, const __half* __restrict__ B,
    uint32_t st, int m0, int n0, int K, int kc, int tid)
{
    const size_t ko = (size_t)kc * 64;
#pragma unroll
    for (int p = 0; p < 4; p++) {
        int c = p*256 + tid;
        int row = c >> 3, kcol = c & 7;
        uint32_t sw = (uint32_t)(row*128 + kcol*16) ^ ((row & 7) << 4);
        cp16(st + sw,         A + (size_t)(m0 + row)*K + ko + kcol*8);
        cp16(st + 16384 + sw, B + (size_t)(n0 + row)*K + ko + kcol*8);
    }
    cp_commit();
}

// OUT: 0 fp32 C; 1 fp16 row-major; 3 fp32 C + head-major fp16; 4 head-major fp16 only
template<int EPI, int OUT>
__device__ __forceinline__ void gemm_core(
    const __half* __restrict__ A, const __half* __restrict__ B,
    const float* __restrict__ bias, float* __restrict__ C,
    __half* __restrict__ Ch, int rowsPerB, int K, int ldc)
{
    extern __shared__ char dsm[];
    const uint32_t sbase = smem_u32(dsm);
    const int tid = threadIdx.x, lane = tid & 31, warp = tid >> 5;
    const int m0 = blockIdx.y * 128, n0 = blockIdx.x * 128;
    const int wm = (warp & 1) * 64, wn = (warp >> 1) * 32;
    const int NC = K >> 6;

    float acc[4][4][4] = {};
    g_load_stage(A, B, sbase,            m0, n0, K, 0, tid);
    g_load_stage(A, B, sbase + GSTAGE,   m0, n0, K, 1, tid);
    g_load_stage(A, B, sbase + 2*GSTAGE, m0, n0, K, 2, tid);
    asm volatile("cp.async.wait_group 2;" ::: "memory");
    __syncthreads();

    const int arow = wm + (lane & 15), akb = lane & 16;
    const int brow = wn + ((lane & 16) >> 1) + (lane & 7), bkb = (lane & 8) << 1;

    int buf = 0;
    for (int kc = 0; kc < NC; kc++) {
        const uint32_t st = sbase + buf * GSTAGE;
#pragma unroll
        for (int ks = 0; ks < 4; ks++) {
            const int kb = ks*32;
            uint32_t ah[4][4], bh[2][4];
#pragma unroll
            for (int im = 0; im < 4; im++) {
                int row = arow + im*16;
                uint32_t off = (uint32_t)(row*128 + kb + akb) ^ ((row & 7) << 4);
                ldsm4(ah[im], st + off);
            }
#pragma unroll
            for (int np = 0; np < 2; np++) {
                int row = brow + np*16;
                uint32_t off = (uint32_t)(row*128 + kb + bkb) ^ ((row & 7) << 4);
                ldsm4(bh[np], st + 16384 + off);
            }
#pragma unroll
            for (int im = 0; im < 4; im++)
#pragma unroll
                for (int in = 0; in < 4; in++) {
                    const int np = in >> 1, hf = (in & 1) * 2;
                    mma16816(acc[im][in], ah[im], bh[np][hf], bh[np][hf+1]);
                }
        }
        __syncthreads();
        if (kc + 3 < NC) {
            g_load_stage(A, B, sbase + buf*GSTAGE, m0, n0, K, kc + 3, tid);
            asm volatile("cp.async.wait_group 2;" ::: "memory");
        } else if (kc + 2 < NC) {
            asm volatile("cp.async.wait_group 1;" ::: "memory");
        } else {
            asm volatile("cp.async.wait_group 0;" ::: "memory");
        }
        __syncthreads();
        buf++; if (buf == 3) buf = 0;
    }

    const int rbase = m0 + wm + (lane >> 2);
    const int cbase = n0 + wn + 2*(lane & 3);
#pragma unroll
    for (int im = 0; im < 4; im++) {
#pragma unroll
        for (int in = 0; in < 4; in++) {
            int col = cbase + in*8;
            float v0 = acc[im][in][0], v1 = acc[im][in][1];
            float v2 = acc[im][in][2], v3 = acc[im][in][3];
            if (EPI >= 1) {
                float b0 = bias[col], b1 = bias[col+1];
                v0 += b0; v1 += b1; v2 += b0; v3 += b1;
            }
            if (EPI == 2) {
                v0 = 0.5f*v0*(1.0f + erff(v0*0.7071067811865476f));
                v1 = 0.5f*v1*(1.0f + erff(v1*0.7071067811865476f));
                v2 = 0.5f*v2*(1.0f + erff(v2*0.7071067811865476f));
                v3 = 0.5f*v3*(1.0f + erff(v3*0.7071067811865476f));
            }
            int r0 = rbase + im*16, r1 = r0 + 8;
            if (OUT == 0 || OUT == 3) {
                *(float2*)(C + (size_t)r0*ldc + col) = make_float2(v0, v1);
                *(float2*)(C + (size_t)r1*ldc + col) = make_float2(v2, v3);
            }
            if (OUT == 1) {
                *(__half2*)(Ch + (size_t)r0*ldc + col) =
                    __halves2half2(__float2half_rn(v0), __float2half_rn(v1));
                *(__half2*)(Ch + (size_t)r1*ldc + col) =
                    __halves2half2(__float2half_rn(v2), __float2half_rn(v3));
            }
            if (OUT >= 3) {
                int nh = col >> 6, d = col & 63;
                size_t d0 = (((size_t)(r0 & 1)*NH + nh)*rowsPerB + (r0 >> 1))*DH + d;
                size_t d1 = (((size_t)(r1 & 1)*NH + nh)*rowsPerB + (r1 >> 1))*DH + d;
                *(__half2*)(Ch + d0) = __halves2half2(__float2half_rn(v0), __float2half_rn(v1));
                *(__half2*)(Ch + d1) = __halves2half2(__float2half_rn(v2), __float2half_rn(v3));
            }
        }
    }
}

template<int EPI, int OUT>
__global__ void __launch_bounds__(256, 2) gemm_mma(
    const __half* __restrict__ A, const __half* __restrict__ B,
    const float* __restrict__ bias, float* __restrict__ C, __half* __restrict__ Ch,
    size_t zsA, size_t zsC, int rowsPerB, int K, int ldc)
{
    const size_t zo = blockIdx.z;
    gemm_core<EPI, OUT>(A + zo*zsA, B, bias,
                        (OUT == 0 || OUT == 3) ? C + zo*zsC : C,
                        (OUT >= 1) ? Ch + zo*zsC : Ch,
                        rowsPerB, K, ldc);
}

__global__ void __launch_bounds__(256, 2) projHKV()
{
    switch (blockIdx.z) {
    case 0: gemm_core<0,4>(g_hb, g_wkT, nullptr, nullptr, g_khh, QL, DM, DM); break;
    case 1: gemm_core<0,0>(g_hb, g_wvT, nullptr, g_v, nullptr, QL, DM, DM); break;
    default: gemm_core<0,4>(g_hb, g_wqT, nullptr, nullptr, g_q1h, QL, DM, DM); break;
    }
}

// ---------------- fused score: S = ac + bk + relshift(bd) + bkr ----------------
#define SF_Q   0
#define SF_K   16384
#define SF_KR  32768
#define SF_SC  65536                 /* float [128][132] = 67584 B */
#define SF_BK  133120
#define SF_BKR 133632
#define SF_SMEM 134656

__global__ void __launch_bounds__(256, 1) score_fused(
    const __half* __restrict__ Q1, const __half* __restrict__ Q2,
    const __half* __restrict__ Kh, const __half* __restrict__ Krh,
    const float* __restrict__ bkT, const float* __restrict__ bkrT,
    float* __restrict__ S)
{
    extern __shared__ char sm[];
    const uint32_t sb = smem_u32(sm);
    float* sc    = (float*)(sm + SF_SC);
    float* bk_s  = (float*)(sm + SF_BK);
    float* bkr_s = (float*)(sm + SF_BKR);
    const int tid = threadIdx.x, lane = tid & 31, warp = tid >> 5;
    const int zz = blockIdx.z, s_ = zz >> 5, bn = zz & 31;
    const __half* Q = s_ ? Q2 : Q1;

    // triangular decode
    int t = blockIdx.x;
    int it = (int)((sqrtf(8.f*t + 1.f) - 1.f) * 0.5f);
    if ((it + 1)*(it + 2)/2 <= t) it++;
    else if (it*(it + 1)/2 > t) it--;
    int jt = t - it*(it + 1)/2;
    const int i0 = it * 128, j0 = jt * 128;
    const int W = 896 + (jt - it) * 128;

    const size_t qb  = ((size_t)bn*QL + i0)*DH;
    const size_t kb  = ((size_t)bn*QL + j0)*DH;
    const size_t krb = ((size_t)bn*RL + W)*DH;
#pragma unroll
    for (int p = 0; p < 4; p++) {
        int c = p*256 + tid;
        int row = c >> 3, kcol = c & 7;
        uint32_t sw = (uint32_t)(row*128 + kcol*16) ^ ((row & 7) << 4);
        cp16(sb + SF_Q + sw, Q  + qb + (size_t)row*DH + kcol*8);
        cp16(sb + SF_K + sw, Kh + kb + (size_t)row*DH + kcol*8);
    }
#pragma unroll
    for (int p = 0; p < 8; p++) {
        int c = p*256 + tid;
        int row = c >> 3, kcol = c & 7;     // row 0..255
        uint32_t sw = (uint32_t)(row*128 + kcol*16) ^ ((row & 7) << 4);
        cp16(sb + SF_KR + sw, Krh + krb + (size_t)row*DH + kcol*8);
    }
    if (tid < 32) cp16(sb + SF_BK + tid*16, bkT + (size_t)bn*QL + j0 + tid*4);
    else if (tid < 96) cp16(sb + SF_BKR + (tid-32)*16, bkrT + (size_t)bn*RL + W + (tid-32)*4);
    cp_commit();
    asm volatile("cp.async.wait_group 0;" ::: "memory");
    __syncthreads();

    const int wm = (warp & 1) * 64, wn = (warp >> 1) * 32;
    const int arow = wm + (lane & 15), akb = lane & 16;
    const int brow = wn + ((lane & 16) >> 1) + (lane & 7), bkb = (lane & 8) << 1;
    const int rb = wm + (lane >> 2), cbx = wn + 2*(lane & 3);

    // ---- ac ----
    {
        float acc[4][4][4] = {};
#pragma unroll
        for (int ks = 0; ks < 4; ks++) {
            const int kbyte = ks*32;
            uint32_t ah[4][4], bh[2][4];
#pragma unroll
            for (int im = 0; im < 4; im++) {
                int row = arow + im*16;
                uint32_t off = (uint32_t)(row*128 + kbyte + akb) ^ ((row & 7) << 4);
                ldsm4(ah[im], sb + SF_Q + off);
            }
#pragma unroll
            for (int np = 0; np < 2; np++) {
                int row = brow + np*16;
                uint32_t off = (uint32_t)(row*128 + kbyte + bkb) ^ ((row & 7) << 4);
                ldsm4(bh[np], sb + SF_K + off);
            }
#pragma unroll
            for (int im = 0; im < 4; im++)
#pragma unroll
                for (int in = 0; in < 4; in++) {
                    const int np = in >> 1, hf = (in & 1) * 2;
                    mma16816(acc[im][in], ah[im], bh[np][hf], bh[np][hf+1]);
                }
        }
#pragma unroll
        for (int im = 0; im < 4; im++)
#pragma unroll
            for (int in = 0; in < 4; in++) {
                int col = cbx + in*8, r0 = rb + im*16;
                sc[r0*132 + col]         = acc[im][in][0] + bk_s[col];
                sc[r0*132 + col + 1]     = acc[im][in][1] + bk_s[col+1];
                sc[(r0+8)*132 + col]     = acc[im][in][2] + bk_s[col];
                sc[(r0+8)*132 + col + 1] = acc[im][in][3] + bk_s[col+1];
            }
    }
    __syncthreads();

    // ---- bd with rel-shift scatter ----
#pragma unroll
    for (int c2 = 0; c2 < 2; c2++) {
        float ab[4][4][4] = {};
#pragma unroll
        for (int ks = 0; ks < 4; ks++) {
            const int kbyte = ks*32;
            uint32_t ah[4][4], bh[2][4];
#pragma unroll
            for (int im = 0; im < 4; im++) {
                int row = arow + im*16;
                uint32_t off = (uint32_t)(row*128 + kbyte + akb) ^ ((row & 7) << 4);
                ldsm4(ah[im], sb + SF_Q + off);
            }
#pragma unroll
            for (int np = 0; np < 2; np++) {
                int row = brow + np*16;
                uint32_t off = (uint32_t)(row*128 + kbyte + bkb) ^ ((row & 7) << 4);
                ldsm4(bh[np], sb + SF_KR + c2*16384 + off);
            }
#pragma unroll
            for (int im = 0; im < 4; im++)
#pragma unroll
                for (int in = 0; in < 4; in++) {
                    const int np = in >> 1, hf = (in & 1) * 2;
                    mma16816(ab[im][in], ah[im], bh[np][hf], bh[np][hf+1]);
                }
        }
#pragma unroll
        for (int im = 0; im < 4; im++)
#pragma unroll
            for (int in = 0; in < 4; in++)
#pragma unroll
                for (int rr = 0; rr < 4; rr++) {
                    int il = rb + im*16 + ((rr >= 2) ? 8 : 0);
                    int tt = c2*128 + cbx + in*8 + (rr & 1);
                    int jl = tt + il - 128;
                    if (jl >= 0 && jl < 128)
                        sc[il*132 + jl] += ab[im][in][rr] + bkr_s[tt];
                }
    }
    __syncthreads();

    // ---- store combined tile ----
    float* Cb = S + (size_t)s_*SSTR + ((size_t)bn << 20) + (size_t)i0*QL + j0;
#pragma unroll
    for (int p = 0; p < 16; p++) {
        int idx4 = p*256 + tid;
        int row = idx4 >> 5, c4 = (idx4 & 31) * 4;
        *(float4*)(Cb + (size_t)row*QL + c4) = *(float4*)(sc + row*132 + c4);
    }
}

// ---------------- fused combine + softmax + fp16 P ----------------
__global__ void __launch_bounds__(256) softmax_fused(
    const float* __restrict__ S, const __half* __restrict__ diff,
    const float* __restrict__ ef, __half* __restrict__ Ph)
{
    __shared__ float red[8];
    const int i = blockIdx.x;
    const int zz = blockIdx.y, s = zz >> 5, bn = zz & 31, b = bn >> 4, n = bn & 15;
    const int jmax = ((i >> 7) + 1) << 7;
    const float* Sr = S + (size_t)s*SSTR + ((size_t)bn << 20) + ((size_t)i << 10);
    const __half* Dr = diff + ((size_t)b << 20) + ((size_t)i << 10);
    const float* efs = ef + (size_t)s*M2*NH*2;
    const float e0 = efs[(((size_t)i*2 + b)*NH + n)*2];
    const float de = efs[(((size_t)i*2 + b)*NH + n)*2 + 1] - e0;
    const int t = threadIdx.x, lane = t & 31, w = t >> 5;

    float v[4];
#pragma unroll
    for (int p = 0; p < 4; p++) {
        int j = t + p*256;
        if (j < jmax) {
            float sc = (Sr[j] + e0 + de*__half2float(Dr[j])) * ATT_SCALE;
            bool blocked = s ? (j >= i) : (j > i);
            v[p] = blocked ? sc - 1e30f : sc;
        } else v[p] = -1e30f;
    }
    float m = fmaxf(fmaxf(v[0], v[1]), fmaxf(v[2], v[3]));
#pragma unroll
    for (int o = 16; o; o >>= 1) m = fmaxf(m, __shfl_xor_sync(0xffffffffu, m, o));
    if (!lane) red[w] = m;
    __syncthreads();
    m = red[lane & 7];
#pragma unroll
    for (int o = 4; o; o >>= 1) m = fmaxf(m, __shfl_xor_sync(0xffffffffu, m, o));
    float sum = 0.f;
#pragma unroll
    for (int p = 0; p < 4; p++) { v[p] = expf(v[p] - m); sum += v[p]; }
#pragma unroll
    for (int o = 16; o; o >>= 1) sum += __shfl_xor_sync(0xffffffffu, sum, o);
    __syncthreads();
    if (!lane) red[w] = sum;
    __syncthreads();
    sum = red[lane & 7];
#pragma unroll
    for (int o = 4; o; o >>= 1) sum += __shfl_xor_sync(0xffffffffu, sum, o);
    const float inv = 1.0f / sum;
    const size_t base = (size_t)s*SSTR + ((size_t)bn << 20) + ((size_t)i << 10);
#pragma unroll
    for (int p = 0; p < 4; p++) {
        int j = t + p*256;
        if (j < jmax) Ph[base + j] = __float2half_rn(v[p] * inv);
    }
}

// ---------------- batched PV GEMM (1-pass, causal K) ----------------
#define PV_STAGE 24576
#define PV_SMEM (2*PV_STAGE)

__device__ __forceinline__ void pv_load(
    const __half* __restrict__ P, const __half* __restrict__ V,
    uint32_t st, size_t pbase, size_t vbase, int kc, int tid)
{
    const size_t ko = (size_t)kc * 64;
#pragma unroll
    for (int p = 0; p < 4; p++) {
        int c = p*256 + tid;
        int row = c >> 3, kcol = c & 7;
        uint32_t sw = (uint32_t)(row*128 + kcol*16) ^ ((row & 7) << 4);
        cp16(st + sw, P + pbase + (size_t)row*QL + ko + kcol*8);
    }
#pragma unroll
    for (int p = 0; p < 2; p++) {
        int c = p*256 + tid;
        int row = c >> 3, kcol = c & 7;
        uint32_t sw = (uint32_t)(row*128 + kcol*16) ^ ((row & 7) << 4);
        cp16(st + 16384 + sw, V + vbase + (size_t)row*QL + ko + kcol*8);
    }
    cp_commit();
}

__global__ void __launch_bounds__(256, 2) pv_mma(
    const __half* __restrict__ P, const __half* __restrict__ V, __half* __restrict__ O)
{
    extern __shared__ char dsm[];
    const uint32_t sbase = smem_u32(dsm);
    const int tid = threadIdx.x, lane = tid & 31, warp = tid >> 5;
    const int zz = blockIdx.y, s = zz >> 5, bn = zz & 31, b = bn >> 4, n = bn & 15;
    const int it = blockIdx.x;
    const int i0 = it * 128;
    const int NC = 2*it + 2;
    const size_t pbase = (size_t)s*SSTR + ((size_t)bn << 20) + (size_t)i0*QL;
    const size_t vbase = (size_t)bn * DH * QL;
    const size_t obase = (size_t)s * M2 * DM;

    float acc[2][4][4] = {};
    pv_load(P, V, sbase,            pbase, vbase, 0, tid);
    pv_load(P, V, sbase + PV_STAGE, pbase, vbase, 1, tid);
    asm volatile("cp.async.wait_group 1;" ::: "memory");
    __syncthreads();

    const int wm = (warp & 3) * 32, wn = (warp >> 2) * 32;
    const int arow = wm + (lane & 15), akb = lane & 16;
    const int brow = wn + ((lane & 16) >> 1) + (lane & 7), bkb = (lane & 8) << 1;

    for (int kc = 0; kc < NC; kc++) {
        const uint32_t st = sbase + (kc & 1) * PV_STAGE;
#pragma unroll
        for (int ks = 0; ks < 4; ks++) {
            const int kb = ks*32;
            uint32_t ah[2][4], bh[2][4];
#pragma unroll
            for (int im = 0; im < 2; im++) {
                int row = arow + im*16;
                uint32_t off = (uint32_t)(row*128 + kb + akb) ^ ((row & 7) << 4);
                ldsm4(ah[im], st + off);
            }
#pragma unroll
            for (int np = 0; np < 2; np++) {
                int row = brow + np*16;
                uint32_t off = (uint32_t)(row*128 + kb + bkb) ^ ((row & 7) << 4);
                ldsm4(bh[np], st + 16384 + off);
            }
#pragma unroll
            for (int im = 0; im < 2; im++)
#pragma unroll
                for (int in = 0; in < 4; in++) {
                    const int np = in >> 1, hf = (in & 1) * 2;
                    mma16816(acc[im][in], ah[im], bh[np][hf], bh[np][hf+1]);
                }
        }
        __syncthreads();
        if (kc + 2 < NC) {
            pv_load(P, V, sbase + (kc & 1)*PV_STAGE, pbase, vbase, kc + 2, tid);
            asm volatile("cp.async.wait_group 1;" ::: "memory");
        } else {
            asm volatile("cp.async.wait_group 0;" ::: "memory");
        }
        __syncthreads();
    }

    const int rl = wm + (lane >> 2);
    const int cb = wn + 2*(lane & 3);
#pragma unroll
    for (int im = 0; im < 2; im++)
#pragma unroll
        for (int in = 0; in < 4; in++) {
            int col = cb + in*8;
            int r0 = i0 + rl + im*16, r1 = r0 + 8;
            *(__half2*)(O + obase + ((size_t)r0*2 + b)*DM + n*DH + col) =
                __halves2half2(__float2half_rn(acc[im][in][0]), __float2half_rn(acc[im][in][1]));
            *(__half2*)(O + obase + ((size_t)r1*2 + b)*DM + n*DH + col) =
                __halves2half2(__float2half_rn(acc[im][in][2]), __float2half_rn(acc[im][in][3]));
        }
}

// ---------------- residual + LayerNorm (merged streams) ----------------
template<int WB16>
__global__ void __launch_bounds__(256) add_ln(
    const float* __restrict__ a, const float* __restrict__ x0, const float* __restrict__ x1,
    const float* __restrict__ gamma, const float* __restrict__ beta,
    float* __restrict__ out, __half* __restrict__ oh)
{
    __shared__ float buf[1024];
    __shared__ float red[8];
    __shared__ float s_stat;
    const size_t base = (size_t)blockIdx.x << 10;
    const int str = blockIdx.x >> 11;
    const size_t lbase = (size_t)(blockIdx.x & 2047) << 10;
    const float* x = str ? x1 : x0;
    const int t = threadIdx.x, lane = t & 31, w = t >> 5;
    float sum = 0.f;
#pragma unroll
    for (int p = 0; p < 4; p++) {
        float v = a[base + t + p*256] + x[lbase + t + p*256];
        buf[t + p*256] = v; sum += v;
    }
#pragma unroll
    for (int o = 16; o; o >>= 1) sum += __shfl_xor_sync(0xffffffffu, sum, o);
    if (!lane) red[w] = sum;
    __syncthreads();
    if (t == 0) { float s = 0; for (int i = 0; i < 8; i++) s += red[i]; s_stat = s * (1.0f/1024.0f); }
    __syncthreads();
    const float mean = s_stat;
    float vs = 0.f;
#pragma unroll
    for (int p = 0; p < 4; p++) { float d = buf[t + p*256] - mean; vs += d*d; }
#pragma unroll
    for (int o = 16; o; o >>= 1) vs += __shfl_xor_sync(0xffffffffu, vs, o);
    __syncthreads();
    if (!lane) red[w] = vs;
    __syncthreads();
    if (t == 0) { float s = 0; for (int i = 0; i < 8; i++) s += red[i]; s_stat = s * (1.0f/1024.0f); }
    __syncthreads();
    const float r = rsqrtf(s_stat + 1e-12f);
#pragma unroll
    for (int p = 0; p < 4; p++) {
        int c = t + p*256;
        float val = (buf[c] - mean) * r * gamma[c] + beta[c];
        out[base + c] = val;
        if (WB16) oh[base + c] = __float2half_rn(val);
    }
}

// ---------------- host ----------------
extern "C" void kernel_launch(void* const* d_in, const int* in_sizes, int n_in,
                              void* d_out, int out_size)
{
    (void)in_sizes; (void)n_in; (void)out_size;
    const float* h       = (const float*)d_in[0];
    const float* g       = (const float*)d_in[1];
    const float* r       = (const float*)d_in[2];
    const float* seg_mat = (const float*)d_in[5];
    const float* wq      = (const float*)d_in[6];
    const float* wk      = (const float*)d_in[7];
    const float* wv      = (const float*)d_in[8];
    const float* wo      = (const float*)d_in[9];
    const float* wr      = (const float*)d_in[10];
    const float* rwb     = (const float*)d_in[11];
    const float* rrb     = (const float*)d_in[12];
    const float* rsb     = (const float*)d_in[13];
    const float* se      = (const float*)d_in[14];
    const float* lnga    = (const float*)d_in[15];
    const float* lnba    = (const float*)d_in[16];
    const float* w1      = (const float*)d_in[17];
    const float* b1      = (const float*)d_in[18];
    const float* w2      = (const float*)d_in[19];
    const float* b2      = (const float*)d_in[20];
    const float* lngf    = (const float*)d_in[21];
    const float* lnbf    = (const float*)d_in[22];

    cudaFuncSetAttribute(projHKV,       cudaFuncAttributeMaxDynamicSharedMemorySize, GSMEM_BYTES);
    cudaFuncSetAttribute(gemm_mma<0,0>, cudaFuncAttributeMaxDynamicSharedMemorySize, GSMEM_BYTES);
    cudaFuncSetAttribute(gemm_mma<0,4>, cudaFuncAttributeMaxDynamicSharedMemorySize, GSMEM_BYTES);
    cudaFuncSetAttribute(gemm_mma<2,1>, cudaFuncAttributeMaxDynamicSharedMemorySize, GSMEM_BYTES);
    cudaFuncSetAttribute(gemm_mma<1,0>, cudaFuncAttributeMaxDynamicSharedMemorySize, GSMEM_BYTES);
    cudaFuncSetAttribute(score_fused,   cudaFuncAttributeMaxDynamicSharedMemorySize, SF_SMEM);
    cudaFuncSetAttribute(pv_mma,        cudaFuncAttributeMaxDynamicSharedMemorySize, PV_SMEM);

    float *v,*ef,*o,*y,*z,*bkT,*bkrT,*S;
    __half *hb,*rb,*gb,*wqT,*wkT,*wvT,*wrT,*woC,*w1T,*w2T,*diffb;
    __half *q1h,*q2h,*khh,*krh,*vth,*Ph,*at,*yh,*th;
    cudaGetSymbolAddress((void**)&v,    g_v);
    cudaGetSymbolAddress((void**)&ef,   g_ef);
    cudaGetSymbolAddress((void**)&o,    g_o);
    cudaGetSymbolAddress((void**)&y,    g_y);
    cudaGetSymbolAddress((void**)&z,    g_z);
    cudaGetSymbolAddress((void**)&bkT,  g_bkT);
    cudaGetSymbolAddress((void**)&bkrT, g_bkrT);
    cudaGetSymbolAddress((void**)&S,    g_S);
    cudaGetSymbolAddress((void**)&diffb,g_diffb);
    cudaGetSymbolAddress((void**)&hb,   g_hb);
    cudaGetSymbolAddress((void**)&rb,   g_rb);
    cudaGetSymbolAddress((void**)&gb,   g_gb);
    cudaGetSymbolAddress((void**)&wqT,  g_wqT);
    cudaGetSymbolAddress((void**)&wkT,  g_wkT);
    cudaGetSymbolAddress((void**)&wvT,  g_wvT);
    cudaGetSymbolAddress((void**)&wrT,  g_wrT);
    cudaGetSymbolAddress((void**)&woC,  g_woC);
    cudaGetSymbolAddress((void**)&w1T,  g_w1T);
    cudaGetSymbolAddress((void**)&w2T,  g_w2T);
    cudaGetSymbolAddress((void**)&q1h,  g_q1h);
    cudaGetSymbolAddress((void**)&q2h,  g_q2h);
    cudaGetSymbolAddress((void**)&khh,  g_khh);
    cudaGetSymbolAddress((void**)&krh,  g_krh);
    cudaGetSymbolAddress((void**)&vth,  g_vth);
    cudaGetSymbolAddress((void**)&Ph,   g_Ph);
    cudaGetSymbolAddress((void**)&at,   g_at);
    cudaGetSymbolAddress((void**)&yh,   g_yh);
    cudaGetSymbolAddress((void**)&th,   g_th);

    dim3 tb(32, 8);
    // 1-4: deps for projHKV; launch 5 = projHKV (ncu target)
    convT4_half<<<dim3(DM/32, DM/32, 4), tb>>>(wk, wv, wq, wr, wkT, wvT, wqT, wrT);
    conv_hg<<<dim3((M2*DM/4 + 255)/256, 2), 256>>>(h, g, hb, gb, M2*DM/4);
    conv_half<<<(MR*DM/4 + 255)/256, 256>>>(r, rb, MR*DM/4);
    conv_half<<<(DM*DM/4 + 255)/256, 256>>>(wo, woC, DM*DM/4);
    projHKV<<<dim3(8, 16, 3), 256, GSMEM_BYTES>>>();

    convT_half<<<dim3(DI/32, DM/32), tb>>>(w1, w1T, DM, DI);
    convT_half<<<dim3(DM/32, DI/32), tb>>>(w2, w2T, DI, DM);
    prep_diff<<<(2*QL*QL + 255)/256, 256>>>(seg_mat, diffb);

    gemm_mma<0,4><<<dim3(8,32,1), 256, GSMEM_BYTES>>>(rb, wrT, nullptr, nullptr, krh, 0, 0, RL, DM, DM);
    gemm_mma<0,4><<<dim3(8,16,1), 256, GSMEM_BYTES>>>(gb, wqT, nullptr, nullptr, q2h, 0, 0, QL, DM, DM);
    repack_vT<<<dim3(QL/32, DH/32, 32), tb>>>(v, vth);

    bias_dotT_h<<<(32*QL*32 + 255)/256, 256>>>(khh, rwb, bkT,  32*QL);
    bias_dotT_h<<<(32*RL*32 + 255)/256, 256>>>(krh, rrb, bkrT, 32*RL);
    ef_kernel_h<<<dim3((M2*NH*32 + 255)/256, 2), 256>>>(q1h, q2h, rsb, se);

    // attention
    score_fused<<<dim3(36, 1, 64), 256, SF_SMEM>>>(q1h, q2h, khh, krh, bkT, bkrT, S);
    softmax_fused<<<dim3(QL, 64), 256>>>(S, diffb, ef, Ph);
    pv_mma<<<dim3(8, 64), 256, PV_SMEM>>>(Ph, vth, at);
    vmean_fix<<<32, 64>>>(v, at);

    // back half
    gemm_mma<0,0><<<dim3(8,16,2), 256, GSMEM_BYTES>>>(at, woC, nullptr, o, nullptr,
        (size_t)M2*DM, (size_t)M2*DM, QL, DM, DM);
    add_ln<1><<<2*M2, 256>>>(o, h, g, lnga, lnba, y, yh);
    gemm_mma<2,1><<<dim3(32,16,2), 256, GSMEM_BYTES>>>(yh, w1T, b1, nullptr, th,
        (size_t)M2*DM, (size_t)M2*DI, QL, DM, DI);
    gemm_mma<1,0><<<dim3(8,16,2), 256, GSMEM_BYTES>>>(th, w2T, b2, z, nullptr,
        (size_t)M2*DI, (size_t)M2*DM, QL, DI, DM);
    add_ln<0><<<2*M2, 256>>>(z, y, y + (size_t)M2*DM, lngf, lnbf, (float*)d_out, nullptr);
}

// round 15
// speedup vs baseline: 1.0331x; 1.0331x over previous
#include <cuda_runtime.h>
#include <cuda_fp16.h>
#include <math.h>
#include <stdint.h>

#define QL 1024
#define NH 16
#define DH 64
#define DM 1024
#define DI 4096
#define RL 2048
#define M2 (QL*2)
#define MR (RL*2)
#define ATT_SCALE 0.125f
#define SSTR ((size_t)32*QL*QL)
#define BSTR ((size_t)32*QL*RL)

__device__ __forceinline__ uint32_t smem_u32(const void* p) {
    uint32_t a;
    asm("{ .reg .u64 t; cvta.to.shared.u64 t, %1; cvt.u32.u64 %0, t; }" : "=r"(a) : "l"(p));
    return a;
}
__device__ __forceinline__ void cp16(uint32_t dst, const void* src) {
    asm volatile("cp.async.cg.shared.global [%0], [%1], 16;" :: "r"(dst), "l"(src));
}
__device__ __forceinline__ void cp_commit() { asm volatile("cp.async.commit_group;" ::: "memory"); }
__device__ __forceinline__ void ldsm4(uint32_t (&r)[4], uint32_t addr) {
    asm volatile("ldmatrix.sync.aligned.m8n8.x4.shared.b16 {%0,%1,%2,%3}, [%4];"
        : "=r"(r[0]), "=r"(r[1]), "=r"(r[2]), "=r"(r[3]) : "r"(addr));
}
__device__ __forceinline__ void mma16816(float (&d)[4], const uint32_t (&a)[4],
                                         uint32_t b0, uint32_t b1) {
    asm volatile("mma.sync.aligned.m16n8k16.row.col.f32.f16.f16.f32 "
        "{%0,%1,%2,%3},{%4,%5,%6,%7},{%8,%9},{%0,%1,%2,%3};"
        : "+f"(d[0]), "+f"(d[1]), "+f"(d[2]), "+f"(d[3])
        : "r"(a[0]), "r"(a[1]), "r"(a[2]), "r"(a[3]), "r"(b0), "r"(b1));
}

// ---------------- scratch ----------------
__device__ float g_v [M2*DM];
__device__ float g_ef[2*M2*NH*2];
__device__ float g_o [2*M2*DM];
__device__ float g_y [2*M2*DM];
__device__ float g_z [2*M2*DM];
__device__ float g_bkT [32*QL];
__device__ float g_bkrT[32*RL];
__device__ float g_S [2*SSTR];
__device__ float g_BD[2*BSTR];
__device__ __align__(256) __half g_diffb[(size_t)2*QL*QL];
__device__ __align__(256) __half g_hb[M2*DM], g_rb[MR*DM], g_gb[M2*DM];
__device__ __align__(256) __half g_wqT[DM*DM], g_wkT[DM*DM], g_wvT[DM*DM];
__device__ __align__(256) __half g_wrT[DM*DM], g_woC[DM*DM];
__device__ __align__(256) __half g_w1T[DM*DI], g_w2T[DI*DM];
__device__ __align__(256) __half g_q1h[32*QL*DH], g_q2h[32*QL*DH];
__device__ __align__(256) __half g_khh[32*QL*DH];
__device__ __align__(256) __half g_krh[32*RL*DH];
__device__ __align__(256) __half g_vth[32*DH*QL];
__device__ __align__(256) __half g_Ph [2*SSTR];
__device__ __align__(256) __half g_at [2*M2*DM];
__device__ __align__(256) __half g_yh [2*M2*DM];
__device__ __align__(256) __half g_th [2*M2*DI];

// ---------------- small kernels ----------------
__global__ void conv_hg(const float* __restrict__ H, const float* __restrict__ G,
                        __half* __restrict__ HB, __half* __restrict__ GB, int n4)
{
    int i = blockIdx.x * blockDim.x + threadIdx.x;
    if (i >= n4) return;
    const float* X = blockIdx.y ? G : H;
    __half* out = blockIdx.y ? GB : HB;
    float4 v = ((const float4*)X)[i];
    ((__half2*)out)[2*i]   = __halves2half2(__float2half_rn(v.x), __float2half_rn(v.y));
    ((__half2*)out)[2*i+1] = __halves2half2(__float2half_rn(v.z), __float2half_rn(v.w));
}

__global__ void conv_half(const float* __restrict__ X, __half* __restrict__ out, int n4)
{
    int i = blockIdx.x * blockDim.x + threadIdx.x;
    if (i >= n4) return;
    float4 v = ((const float4*)X)[i];
    ((__half2*)out)[2*i]   = __halves2half2(__float2half_rn(v.x), __float2half_rn(v.y));
    ((__half2*)out)[2*i+1] = __halves2half2(__float2half_rn(v.z), __float2half_rn(v.w));
}

__global__ void convT4_half(const float* __restrict__ W0, const float* __restrict__ W1,
                            const float* __restrict__ W2, const float* __restrict__ W3,
                            __half* __restrict__ O0, __half* __restrict__ O1,
                            __half* __restrict__ O2, __half* __restrict__ O3)
{
    __shared__ float t[32][33];
    const float* W = (blockIdx.z == 0) ? W0 : (blockIdx.z == 1) ? W1 : (blockIdx.z == 2) ? W2 : W3;
    __half* out    = (blockIdx.z == 0) ? O0 : (blockIdx.z == 1) ? O1 : (blockIdx.z == 2) ? O2 : O3;
    int k0 = blockIdx.y * 32, n0 = blockIdx.x * 32;
    int tx = threadIdx.x, ty = threadIdx.y;
#pragma unroll
    for (int p = 0; p < 4; p++)
        t[ty + p*8][tx] = W[(size_t)(k0 + ty + p*8)*DM + n0 + tx];
    __syncthreads();
#pragma unroll
    for (int p = 0; p < 4; p++)
        out[(size_t)(n0 + ty + p*8)*DM + k0 + tx] = __float2half_rn(t[tx][ty + p*8]);
}

__global__ void convT_half(const float* __restrict__ W, __half* __restrict__ out, int K, int N)
{
    __shared__ float t[32][33];
    int k0 = blockIdx.y * 32, n0 = blockIdx.x * 32;
    int tx = threadIdx.x, ty = threadIdx.y;
#pragma unroll
    for (int p = 0; p < 4; p++)
        t[ty + p*8][tx] = W[(size_t)(k0 + ty + p*8)*N + n0 + tx];
    __syncthreads();
#pragma unroll
    for (int p = 0; p < 4; p++)
        out[(size_t)(n0 + ty + p*8)*K + k0 + tx] = __float2half_rn(t[tx][ty + p*8]);
}

__global__ void repack_vT(const float* __restrict__ V, __half* __restrict__ out)
{
    __shared__ float tile[32][33];
    int j0 = blockIdx.x * 32, d0 = blockIdx.y * 32;
    int bn = blockIdx.z, b = bn >> 4, n = bn & 15;
    int tx = threadIdx.x, ty = threadIdx.y;
#pragma unroll
    for (int p = 0; p < 4; p++)
        tile[ty + p*8][tx] = V[((size_t)(j0 + ty + p*8)*2 + b)*DM + n*DH + d0 + tx];
    __syncthreads();
#pragma unroll
    for (int p = 0; p < 4; p++)
        out[((size_t)bn*DH + d0 + ty + p*8)*QL + j0 + tx] = __float2half_rn(tile[tx][ty + p*8]);
}

__global__ void prep_diff(const float* __restrict__ seg_mat, __half* __restrict__ diff)
{
    size_t idx = (size_t)blockIdx.x * blockDim.x + threadIdx.x;
    if (idx >= (size_t)2*QL*QL) return;
    int j = idx & 1023, i = (idx >> 10) & 1023, b = (int)(idx >> 20);
    diff[idx] = __float2half_rn(seg_mat[(((size_t)i*QL + j)*2 + b)*2 + 1]);
}

__global__ void bias_dotT_h(const __half* __restrict__ X, const float* __restrict__ bias,
                            float* __restrict__ outT, int total)
{
    const int gw = (blockIdx.x * blockDim.x + threadIdx.x) >> 5;
    const int lane = threadIdx.x & 31;
    if (gw >= total) return;
    const int rows = total >> 5;
    const int bn = gw / rows;
    const int nn = bn & 15;
    float s = bias[nn*DH + lane]      * __half2float(X[(size_t)gw*DH + lane])
            + bias[nn*DH + 32 + lane] * __half2float(X[(size_t)gw*DH + 32 + lane]);
#pragma unroll
    for (int o = 16; o; o >>= 1) s += __shfl_xor_sync(0xffffffffu, s, o);
    if (!lane) outT[gw] = s;
}

__global__ void ef_kernel_h(const __half* __restrict__ Q1, const __half* __restrict__ Q2,
                            const float* __restrict__ rsb, const float* __restrict__ se)
{
    const int gw = (blockIdx.x * blockDim.x + threadIdx.x) >> 5;
    const int lane = threadIdx.x & 31;
    if (gw >= M2 * NH) return;
    const __half* qh = blockIdx.y ? Q2 : Q1;
    float* ef = g_ef + (size_t)blockIdx.y * M2 * NH * 2;
    const int i = gw >> 5, b = (gw >> 4) & 1, n = gw & 15;
    const size_t qb = ((size_t)(b*16 + n)*QL + i)*DH;
    const float v0 = __half2float(qh[qb + lane])      + rsb[n*DH + lane];
    const float v1 = __half2float(qh[qb + 32 + lane]) + rsb[n*DH + 32 + lane];
    float s0 = v0*se[n*DH + lane] + v1*se[n*DH + 32 + lane];
    float s1 = v0*se[NH*DH + n*DH + lane] + v1*se[NH*DH + n*DH + 32 + lane];
#pragma unroll
    for (int o = 16; o; o >>= 1) {
        s0 += __shfl_xor_sync(0xffffffffu, s0, o);
        s1 += __shfl_xor_sync(0xffffffffu, s1, o);
    }
    if (!lane) { ef[gw*2] = s0; ef[gw*2 + 1] = s1; }
}

__global__ void vmean_fix(const float* __restrict__ V, __half* __restrict__ O)
{
    int bn = blockIdx.x, b = bn >> 4, n = bn & 15;
    int d = threadIdx.x;
    float s = 0.f;
    for (int j = 0; j < QL; j++) s += V[((size_t)j*2 + b)*DM + n*DH + d];
    s *= (1.0f/1024.0f);
    O[(size_t)M2*DM + (size_t)b*DM + n*DH + d] = __float2half_rn(s);
}

// ---------------- dense GEMM: 1-pass fp16, 3-stage, 2 CTA/SM ----------------
#define GSTAGE 32768
#define GSMEM_BYTES (3*GSTAGE)

__device__ __forceinline__ void g_load_stage(
    const __half* __restrict__ A, const __half* __restrict__ B,
    uint32_t st, int m0, int n0, int K, int kc, int tid)
{
    const size_t ko = (size_t)kc * 64;
#pragma unroll
    for (int p = 0; p < 4; p++) {
        int c = p*256 + tid;
        int row = c >> 3, kcol = c & 7;
        uint32_t sw = (uint32_t)(row*128 + kcol*16) ^ ((row & 7) << 4);
        cp16(st + sw,         A + (size_t)(m0 + row)*K + ko + kcol*8);
        cp16(st + 16384 + sw, B + (size_t)(n0 + row)*K + ko + kcol*8);
    }
    cp_commit();
}

// OUT: 0 fp32 C; 1 fp16 row-major; 3 fp32 C + head-major fp16; 4 head-major fp16 only
template<int EPI, int OUT>
__device__ __forceinline__ void gemm_core(
    const __half* __restrict__ A, const __half* __restrict__ B,
    const float* __restrict__ bias, float* __restrict__ C,
    __half* __restrict__ Ch, int rowsPerB, int K, int ldc)
{
    extern __shared__ char dsm[];
    const uint32_t sbase = smem_u32(dsm);
    const int tid = threadIdx.x, lane = tid & 31, warp = tid >> 5;
    const int m0 = blockIdx.y * 128, n0 = blockIdx.x * 128;
    const int wm = (warp & 1) * 64, wn = (warp >> 1) * 32;
    const int NC = K >> 6;

    float acc[4][4][4] = {};
    g_load_stage(A, B, sbase,            m0, n0, K, 0, tid);
    g_load_stage(A, B, sbase + GSTAGE,   m0, n0, K, 1, tid);
    g_load_stage(A, B, sbase + 2*GSTAGE, m0, n0, K, 2, tid);
    asm volatile("cp.async.wait_group 2;" ::: "memory");
    __syncthreads();

    const int arow = wm + (lane & 15), akb = lane & 16;
    const int brow = wn + ((lane & 16) >> 1) + (lane & 7), bkb = (lane & 8) << 1;

    int buf = 0;
    for (int kc = 0; kc < NC; kc++) {
        const uint32_t st = sbase + buf * GSTAGE;
#pragma unroll
        for (int ks = 0; ks < 4; ks++) {
            const int kb = ks*32;
            uint32_t ah[4][4], bh[2][4];
#pragma unroll
            for (int im = 0; im < 4; im++) {
                int row = arow + im*16;
                uint32_t off = (uint32_t)(row*128 + kb + akb) ^ ((row & 7) << 4);
                ldsm4(ah[im], st + off);
            }
#pragma unroll
            for (int np = 0; np < 2; np++) {
                int row = brow + np*16;
                uint32_t off = (uint32_t)(row*128 + kb + bkb) ^ ((row & 7) << 4);
                ldsm4(bh[np], st + 16384 + off);
            }
#pragma unroll
            for (int im = 0; im < 4; im++)
#pragma unroll
                for (int in = 0; in < 4; in++) {
                    const int np = in >> 1, hf = (in & 1) * 2;
                    mma16816(acc[im][in], ah[im], bh[np][hf], bh[np][hf+1]);
                }
        }
        __syncthreads();
        if (kc + 3 < NC) {
            g_load_stage(A, B, sbase + buf*GSTAGE, m0, n0, K, kc + 3, tid);
            asm volatile("cp.async.wait_group 2;" ::: "memory");
        } else if (kc + 2 < NC) {
            asm volatile("cp.async.wait_group 1;" ::: "memory");
        } else {
            asm volatile("cp.async.wait_group 0;" ::: "memory");
        }
        __syncthreads();
        buf++; if (buf == 3) buf = 0;
    }

    const int rbase = m0 + wm + (lane >> 2);
    const int cbase = n0 + wn + 2*(lane & 3);
#pragma unroll
    for (int im = 0; im < 4; im++) {
#pragma unroll
        for (int in = 0; in < 4; in++) {
            int col = cbase + in*8;
            float v0 = acc[im][in][0], v1 = acc[im][in][1];
            float v2 = acc[im][in][2], v3 = acc[im][in][3];
            if (EPI >= 1) {
                float b0 = bias[col], b1 = bias[col+1];
                v0 += b0; v1 += b1; v2 += b0; v3 += b1;
            }
            if (EPI == 2) {
                v0 = 0.5f*v0*(1.0f + erff(v0*0.7071067811865476f));
                v1 = 0.5f*v1*(1.0f + erff(v1*0.7071067811865476f));
                v2 = 0.5f*v2*(1.0f + erff(v2*0.7071067811865476f));
                v3 = 0.5f*v3*(1.0f + erff(v3*0.7071067811865476f));
            }
            int r0 = rbase + im*16, r1 = r0 + 8;
            if (OUT == 0 || OUT == 3) {
                *(float2*)(C + (size_t)r0*ldc + col) = make_float2(v0, v1);
                *(float2*)(C + (size_t)r1*ldc + col) = make_float2(v2, v3);
            }
            if (OUT == 1) {
                *(__half2*)(Ch + (size_t)r0*ldc + col) =
                    __halves2half2(__float2half_rn(v0), __float2half_rn(v1));
                *(__half2*)(Ch + (size_t)r1*ldc + col) =
                    __halves2half2(__float2half_rn(v2), __float2half_rn(v3));
            }
            if (OUT >= 3) {
                int nh = col >> 6, d = col & 63;
                size_t d0 = (((size_t)(r0 & 1)*NH + nh)*rowsPerB + (r0 >> 1))*DH + d;
                size_t d1 = (((size_t)(r1 & 1)*NH + nh)*rowsPerB + (r1 >> 1))*DH + d;
                *(__half2*)(Ch + d0) = __halves2half2(__float2half_rn(v0), __float2half_rn(v1));
                *(__half2*)(Ch + d1) = __halves2half2(__float2half_rn(v2), __float2half_rn(v3));
            }
        }
    }
}

template<int EPI, int OUT>
__global__ void __launch_bounds__(256, 2) gemm_mma(
    const __half* __restrict__ A, const __half* __restrict__ B,
    const float* __restrict__ bias, float* __restrict__ C, __half* __restrict__ Ch,
    size_t zsA, size_t zsC, int rowsPerB, int K, int ldc)
{
    const size_t zo = blockIdx.z;
    gemm_core<EPI, OUT>(A + zo*zsA, B, bias,
                        (OUT == 0 || OUT == 3) ? C + zo*zsC : C,
                        (OUT >= 1) ? Ch + zo*zsC : Ch,
                        rowsPerB, K, ldc);
}

__global__ void __launch_bounds__(256, 2) projHKV()
{
    switch (blockIdx.z) {
    case 0: gemm_core<0,4>(g_hb, g_wkT, nullptr, nullptr, g_khh, QL, DM, DM); break;
    case 1: gemm_core<0,0>(g_hb, g_wvT, nullptr, g_v, nullptr, QL, DM, DM); break;
    default: gemm_core<0,4>(g_hb, g_wqT, nullptr, nullptr, g_q1h, QL, DM, DM); break;
    }
}

// ---------------- batched score GEMM (1-pass), causal-pruned ----------------
#define SC_SMEM 32768

__global__ void __launch_bounds__(256, 2) score_mma(
    const __half* __restrict__ Q1, const __half* __restrict__ Q2,
    const __half* __restrict__ Km, const float* __restrict__ biasT,
    float* __restrict__ C, size_t zsC, int Ncols, int window)
{
    extern __shared__ char dsm[];
    const uint32_t st = smem_u32(dsm);
    const int tid = threadIdx.x, lane = tid & 31, warp = tid >> 5;
    const int zz = blockIdx.z, s = zz >> 5, bn = zz & 31;
    const __half* Q = s ? Q2 : Q1;
    C += (size_t)s * zsC;

    int i0, j0;
    if (!window) {
        int t = blockIdx.x;
        int it = (int)((sqrtf(8.f*t + 1.f) - 1.f) * 0.5f);
        if ((it + 1)*(it + 2)/2 <= t) it++;
        else if (it*(it + 1)/2 > t) it--;
        int jt = t - it*(it + 1)/2;
        i0 = it * 128; j0 = jt * 128;
    } else {
        int it = blockIdx.y;
        int bx = blockIdx.x;
        if (bx > it + 1) return;
        i0 = it * 128;
        j0 = (7 - it + bx) * 128;
    }

    const size_t qb = ((size_t)bn*QL + i0)*DH;
    const size_t kb = ((size_t)bn*Ncols + j0)*DH;
#pragma unroll
    for (int p = 0; p < 4; p++) {
        int c = p*256 + tid;
        int row = c >> 3, kcol = c & 7;
        uint32_t sw = (uint32_t)(row*128 + kcol*16) ^ ((row & 7) << 4);
        cp16(st + sw,         Q  + qb + (size_t)row*DH + kcol*8);
        cp16(st + 16384 + sw, Km + kb + (size_t)row*DH + kcol*8);
    }
    cp_commit();
    asm volatile("cp.async.wait_group 0;" ::: "memory");
    __syncthreads();

    const int wm = (warp & 1) * 64, wn = (warp >> 1) * 32;
    const int arow = wm + (lane & 15), akb = lane & 16;
    const int brow = wn + ((lane & 16) >> 1) + (lane & 7), bkb = (lane & 8) << 1;

    float acc[4][4][4] = {};
#pragma unroll
    for (int ks = 0; ks < 4; ks++) {
        const int kbyte = ks*32;
        uint32_t ah[4][4], bh[2][4];
#pragma unroll
        for (int im = 0; im < 4; im++) {
            int row = arow + im*16;
            uint32_t off = (uint32_t)(row*128 + kbyte + akb) ^ ((row & 7) << 4);
            ldsm4(ah[im], st + off);
        }
#pragma unroll
        for (int np = 0; np < 2; np++) {
            int row = brow + np*16;
            uint32_t off = (uint32_t)(row*128 + kbyte + bkb) ^ ((row & 7) << 4);
            ldsm4(bh[np], st + 16384 + off);
        }
#pragma unroll
        for (int im = 0; im < 4; im++)
#pragma unroll
            for (int in = 0; in < 4; in++) {
                const int np = in >> 1, hf = (in & 1) * 2;
                mma16816(acc[im][in], ah[im], bh[np][hf], bh[np][hf+1]);
            }
    }

    float* Cb = C + (size_t)bn*QL*Ncols;
    const float* bt = biasT + (size_t)bn*Ncols;
    const int rbase = i0 + wm + (lane >> 2);
    const int cbase = j0 + wn + 2*(lane & 3);
#pragma unroll
    for (int im = 0; im < 4; im++)
#pragma unroll
        for (int in = 0; in < 4; in++) {
            int col = cbase + in*8;
            float b0 = bt[col], b1 = bt[col+1];
            int r0 = rbase + im*16, r1 = r0 + 8;
            *(float2*)(Cb + (size_t)r0*Ncols + col) =
                make_float2(acc[im][in][0] + b0, acc[im][in][1] + b1);
            *(float2*)(Cb + (size_t)r1*Ncols + col) =
                make_float2(acc[im][in][2] + b0, acc[im][in][3] + b1);
        }
}

// ---------------- fused combine + softmax + fp16 P ----------------
__global__ void __launch_bounds__(256) softmax_fused(
    const float* __restrict__ S, const float* __restrict__ BD,
    const __half* __restrict__ diff, const float* __restrict__ ef,
    __half* __restrict__ Ph)
{
    __shared__ float red[8];
    const int i = blockIdx.x;
    const int zz = blockIdx.y, s = zz >> 5, bn = zz & 31, b = bn >> 4, n = bn & 15;
    const int jmax = ((i >> 7) + 1) << 7;
    const float* Sr = S  + (size_t)s*SSTR + ((size_t)bn << 20) + ((size_t)i << 10);
    const float* Br = BD + (size_t)s*BSTR + ((size_t)bn << 21) + ((size_t)i << 11) + (QL - i);
    const __half* Dr = diff + ((size_t)b << 20) + ((size_t)i << 10);
    const float* efs = ef + (size_t)s*M2*NH*2;
    const float e0 = efs[(((size_t)i*2 + b)*NH + n)*2];
    const float de = efs[(((size_t)i*2 + b)*NH + n)*2 + 1] - e0;
    const int t = threadIdx.x, lane = t & 31, w = t >> 5;

    float v[4];
#pragma unroll
    for (int p = 0; p < 4; p++) {
        int j = t + p*256;
        if (j < jmax) {
            float sc = (Sr[j] + Br[j] + e0 + de*__half2float(Dr[j])) * ATT_SCALE;
            bool blocked = s ? (j >= i) : (j > i);
            v[p] = blocked ? sc - 1e30f : sc;
        } else v[p] = -1e30f;
    }
    float m = fmaxf(fmaxf(v[0], v[1]), fmaxf(v[2], v[3]));
#pragma unroll
    for (int o = 16; o; o >>= 1) m = fmaxf(m, __shfl_xor_sync(0xffffffffu, m, o));
    if (!lane) red[w] = m;
    __syncthreads();
    m = red[lane & 7];
#pragma unroll
    for (int o = 4; o; o >>= 1) m = fmaxf(m, __shfl_xor_sync(0xffffffffu, m, o));
    float sum = 0.f;
#pragma unroll
    for (int p = 0; p < 4; p++) { v[p] = expf(v[p] - m); sum += v[p]; }
#pragma unroll
    for (int o = 16; o; o >>= 1) sum += __shfl_xor_sync(0xffffffffu, sum, o);
    __syncthreads();
    if (!lane) red[w] = sum;
    __syncthreads();
    sum = red[lane & 7];
#pragma unroll
    for (int o = 4; o; o >>= 1) sum += __shfl_xor_sync(0xffffffffu, sum, o);
    const float inv = 1.0f / sum;
    const size_t base = (size_t)s*SSTR + ((size_t)bn << 20) + ((size_t)i << 10);
#pragma unroll
    for (int p = 0; p < 4; p++) {
        int j = t + p*256;
        if (j < jmax) Ph[base + j] = __float2half_rn(v[p] * inv);
    }
}

// ---------------- batched PV GEMM (1-pass, causal K) ----------------
#define PV_STAGE 24576
#define PV_SMEM (2*PV_STAGE)

__device__ __forceinline__ void pv_load(
    const __half* __restrict__ P, const __half* __restrict__ V,
    uint32_t st, size_t pbase, size_t vbase, int kc, int tid)
{
    const size_t ko = (size_t)kc * 64;
#pragma unroll
    for (int p = 0; p < 4; p++) {
        int c = p*256 + tid;
        int row = c >> 3, kcol = c & 7;
        uint32_t sw = (uint32_t)(row*128 + kcol*16) ^ ((row & 7) << 4);
        cp16(st + sw, P + pbase + (size_t)row*QL + ko + kcol*8);
    }
#pragma unroll
    for (int p = 0; p < 2; p++) {
        int c = p*256 + tid;
        int row = c >> 3, kcol = c & 7;
        uint32_t sw = (uint32_t)(row*128 + kcol*16) ^ ((row & 7) << 4);
        cp16(st + 16384 + sw, V + vbase + (size_t)row*QL + ko + kcol*8);
    }
    cp_commit();
}

__global__ void __launch_bounds__(256, 2) pv_mma(
    const __half* __restrict__ P, const __half* __restrict__ V, __half* __restrict__ O)
{
    extern __shared__ char dsm[];
    const uint32_t sbase = smem_u32(dsm);
    const int tid = threadIdx.x, lane = tid & 31, warp = tid >> 5;
    const int zz = blockIdx.y, s = zz >> 5, bn = zz & 31, b = bn >> 4, n = bn & 15;
    const int it = blockIdx.x;
    const int i0 = it * 128;
    const int NC = 2*it + 2;
    const size_t pbase = (size_t)s*SSTR + ((size_t)bn << 20) + (size_t)i0*QL;
    const size_t vbase = (size_t)bn * DH * QL;
    const size_t obase = (size_t)s * M2 * DM;

    float acc[2][4][4] = {};
    pv_load(P, V, sbase,            pbase, vbase, 0, tid);
    pv_load(P, V, sbase + PV_STAGE, pbase, vbase, 1, tid);
    asm volatile("cp.async.wait_group 1;" ::: "memory");
    __syncthreads();

    const int wm = (warp & 3) * 32, wn = (warp >> 2) * 32;
    const int arow = wm + (lane & 15), akb = lane & 16;
    const int brow = wn + ((lane & 16) >> 1) + (lane & 7), bkb = (lane & 8) << 1;

    for (int kc = 0; kc < NC; kc++) {
        const uint32_t st = sbase + (kc & 1) * PV_STAGE;
#pragma unroll
        for (int ks = 0; ks < 4; ks++) {
            const int kb = ks*32;
            uint32_t ah[2][4], bh[2][4];
#pragma unroll
            for (int im = 0; im < 2; im++) {
                int row = arow + im*16;
                uint32_t off = (uint32_t)(row*128 + kb + akb) ^ ((row & 7) << 4);
                ldsm4(ah[im], st + off);
            }
#pragma unroll
            for (int np = 0; np < 2; np++) {
                int row = brow + np*16;
                uint32_t off = (uint32_t)(row*128 + kb + bkb) ^ ((row & 7) << 4);
                ldsm4(bh[np], st + 16384 + off);
            }
#pragma unroll
            for (int im = 0; im < 2; im++)
#pragma unroll
                for (int in = 0; in < 4; in++) {
                    const int np = in >> 1, hf = (in & 1) * 2;
                    mma16816(acc[im][in], ah[im], bh[np][hf], bh[np][hf+1]);
                }
        }
        __syncthreads();
        if (kc + 2 < NC) {
            pv_load(P, V, sbase + (kc & 1)*PV_STAGE, pbase, vbase, kc + 2, tid);
            asm volatile("cp.async.wait_group 1;" ::: "memory");
        } else {
            asm volatile("cp.async.wait_group 0;" ::: "memory");
        }
        __syncthreads();
    }

    const int rl = wm + (lane >> 2);
    const int cb = wn + 2*(lane & 3);
#pragma unroll
    for (int im = 0; im < 2; im++)
#pragma unroll
        for (int in = 0; in < 4; in++) {
            int col = cb + in*8;
            int r0 = i0 + rl + im*16, r1 = r0 + 8;
            *(__half2*)(O + obase + ((size_t)r0*2 + b)*DM + n*DH + col) =
                __halves2half2(__float2half_rn(acc[im][in][0]), __float2half_rn(acc[im][in][1]));
            *(__half2*)(O + obase + ((size_t)r1*2 + b)*DM + n*DH + col) =
                __halves2half2(__float2half_rn(acc[im][in][2]), __float2half_rn(acc[im][in][3]));
        }
}

// ---------------- residual + LayerNorm (merged streams) ----------------
template<int WB16>
__global__ void __launch_bounds__(256) add_ln(
    const float* __restrict__ a, const float* __restrict__ x0, const float* __restrict__ x1,
    const float* __restrict__ gamma, const float* __restrict__ beta,
    float* __restrict__ out, __half* __restrict__ oh)
{
    __shared__ float buf[1024];
    __shared__ float red[8];
    __shared__ float s_stat;
    const size_t base = (size_t)blockIdx.x << 10;
    const int str = blockIdx.x >> 11;
    const size_t lbase = (size_t)(blockIdx.x & 2047) << 10;
    const float* x = str ? x1 : x0;
    const int t = threadIdx.x, lane = t & 31, w = t >> 5;
    float sum = 0.f;
#pragma unroll
    for (int p = 0; p < 4; p++) {
        float v = a[base + t + p*256] + x[lbase + t + p*256];
        buf[t + p*256] = v; sum += v;
    }
#pragma unroll
    for (int o = 16; o; o >>= 1) sum += __shfl_xor_sync(0xffffffffu, sum, o);
    if (!lane) red[w] = sum;
    __syncthreads();
    if (t == 0) { float s = 0; for (int i = 0; i < 8; i++) s += red[i]; s_stat = s * (1.0f/1024.0f); }
    __syncthreads();
    const float mean = s_stat;
    float vs = 0.f;
#pragma unroll
    for (int p = 0; p < 4; p++) { float d = buf[t + p*256] - mean; vs += d*d; }
#pragma unroll
    for (int o = 16; o; o >>= 1) vs += __shfl_xor_sync(0xffffffffu, vs, o);
    __syncthreads();
    if (!lane) red[w] = vs;
    __syncthreads();
    if (t == 0) { float s = 0; for (int i = 0; i < 8; i++) s += red[i]; s_stat = s * (1.0f/1024.0f); }
    __syncthreads();
    const float r = rsqrtf(s_stat + 1e-12f);
#pragma unroll
    for (int p = 0; p < 4; p++) {
        int c = t + p*256;
        float val = (buf[c] - mean) * r * gamma[c] + beta[c];
        out[base + c] = val;
        if (WB16) oh[base + c] = __float2half_rn(val);
    }
}

// ---------------- host ----------------
extern "C" void kernel_launch(void* const* d_in, const int* in_sizes, int n_in,
                              void* d_out, int out_size)
{
    (void)in_sizes; (void)n_in; (void)out_size;
    const float* h       = (const float*)d_in[0];
    const float* g       = (const float*)d_in[1];
    const float* r       = (const float*)d_in[2];
    const float* seg_mat = (const float*)d_in[5];
    const float* wq      = (const float*)d_in[6];
    const float* wk      = (const float*)d_in[7];
    const float* wv      = (const float*)d_in[8];
    const float* wo      = (const float*)d_in[9];
    const float* wr      = (const float*)d_in[10];
    const float* rwb     = (const float*)d_in[11];
    const float* rrb     = (const float*)d_in[12];
    const float* rsb     = (const float*)d_in[13];
    const float* se      = (const float*)d_in[14];
    const float* lnga    = (const float*)d_in[15];
    const float* lnba    = (const float*)d_in[16];
    const float* w1      = (const float*)d_in[17];
    const float* b1      = (const float*)d_in[18];
    const float* w2      = (const float*)d_in[19];
    const float* b2      = (const float*)d_in[20];
    const float* lngf    = (const float*)d_in[21];
    const float* lnbf    = (const float*)d_in[22];

    cudaFuncSetAttribute(projHKV,       cudaFuncAttributeMaxDynamicSharedMemorySize, GSMEM_BYTES);
    cudaFuncSetAttribute(gemm_mma<0,0>, cudaFuncAttributeMaxDynamicSharedMemorySize, GSMEM_BYTES);
    cudaFuncSetAttribute(gemm_mma<0,4>, cudaFuncAttributeMaxDynamicSharedMemorySize, GSMEM_BYTES);
    cudaFuncSetAttribute(gemm_mma<2,1>, cudaFuncAttributeMaxDynamicSharedMemorySize, GSMEM_BYTES);
    cudaFuncSetAttribute(gemm_mma<1,0>, cudaFuncAttributeMaxDynamicSharedMemorySize, GSMEM_BYTES);
    cudaFuncSetAttribute(score_mma,     cudaFuncAttributeMaxDynamicSharedMemorySize, SC_SMEM);
    cudaFuncSetAttribute(pv_mma,        cudaFuncAttributeMaxDynamicSharedMemorySize, PV_SMEM);

    float *v,*ef,*o,*y,*z,*bkT,*bkrT,*S,*BD;
    __half *hb,*rb,*gb,*wqT,*wkT,*wvT,*wrT,*woC,*w1T,*w2T,*diffb;
    __half *q1h,*q2h,*khh,*krh,*vth,*Ph,*at,*yh,*th;
    cudaGetSymbolAddress((void**)&v,    g_v);
    cudaGetSymbolAddress((void**)&ef,   g_ef);
    cudaGetSymbolAddress((void**)&o,    g_o);
    cudaGetSymbolAddress((void**)&y,    g_y);
    cudaGetSymbolAddress((void**)&z,    g_z);
    cudaGetSymbolAddress((void**)&bkT,  g_bkT);
    cudaGetSymbolAddress((void**)&bkrT, g_bkrT);
    cudaGetSymbolAddress((void**)&S,    g_S);
    cudaGetSymbolAddress((void**)&BD,   g_BD);
    cudaGetSymbolAddress((void**)&diffb,g_diffb);
    cudaGetSymbolAddress((void**)&hb,   g_hb);
    cudaGetSymbolAddress((void**)&rb,   g_rb);
    cudaGetSymbolAddress((void**)&gb,   g_gb);
    cudaGetSymbolAddress((void**)&wqT,  g_wqT);
    cudaGetSymbolAddress((void**)&wkT,  g_wkT);
    cudaGetSymbolAddress((void**)&wvT,  g_wvT);
    cudaGetSymbolAddress((void**)&wrT,  g_wrT);
    cudaGetSymbolAddress((void**)&woC,  g_woC);
    cudaGetSymbolAddress((void**)&w1T,  g_w1T);
    cudaGetSymbolAddress((void**)&w2T,  g_w2T);
    cudaGetSymbolAddress((void**)&q1h,  g_q1h);
    cudaGetSymbolAddress((void**)&q2h,  g_q2h);
    cudaGetSymbolAddress((void**)&khh,  g_khh);
    cudaGetSymbolAddress((void**)&krh,  g_krh);
    cudaGetSymbolAddress((void**)&vth,  g_vth);
    cudaGetSymbolAddress((void**)&Ph,   g_Ph);
    cudaGetSymbolAddress((void**)&at,   g_at);
    cudaGetSymbolAddress((void**)&yh,   g_yh);
    cudaGetSymbolAddress((void**)&th,   g_th);

    dim3 tb(32, 8);
    convT4_half<<<dim3(DM/32, DM/32, 4), tb>>>(wk, wv, wq, wr, wkT, wvT, wqT, wrT);
    conv_hg<<<dim3((M2*DM/4 + 255)/256, 2), 256>>>(h, g, hb, gb, M2*DM/4);
    conv_half<<<(MR*DM/4 + 255)/256, 256>>>(r, rb, MR*DM/4);
    conv_half<<<(DM*DM/4 + 255)/256, 256>>>(wo, woC, DM*DM/4);
    projHKV<<<dim3(8, 16, 3), 256, GSMEM_BYTES>>>();

    convT_half<<<dim3(DI/32, DM/32), tb>>>(w1, w1T, DM, DI);
    convT_half<<<dim3(DM/32, DI/32), tb>>>(w2, w2T, DI, DM);
    prep_diff<<<(2*QL*QL + 255)/256, 256>>>(seg_mat, diffb);

    gemm_mma<0,4><<<dim3(8,32,1), 256, GSMEM_BYTES>>>(rb, wrT, nullptr, nullptr, krh, 0, 0, RL, DM, DM);
    gemm_mma<0,4><<<dim3(8,16,1), 256, GSMEM_BYTES>>>(gb, wqT, nullptr, nullptr, q2h, 0, 0, QL, DM, DM);
    repack_vT<<<dim3(QL/32, DH/32, 32), tb>>>(v, vth);

    bias_dotT_h<<<(32*QL*32 + 255)/256, 256>>>(khh, rwb, bkT,  32*QL);
    bias_dotT_h<<<(32*RL*32 + 255)/256, 256>>>(krh, rrb, bkrT, 32*RL);
    ef_kernel_h<<<dim3((M2*NH*32 + 255)/256, 2), 256>>>(q1h, q2h, rsb, se);

    // attention (R12 structure: split ac + windowed bd, causal-pruned, 1-pass fp16)
    score_mma<<<dim3(36, 1, 64), 256, SC_SMEM>>>(q1h, q2h, khh, bkT,  S,  SSTR, QL, 0);
    score_mma<<<dim3(9, 8, 64), 256, SC_SMEM>>>(q1h, q2h, krh, bkrT, BD, BSTR, RL, 1);
    softmax_fused<<<dim3(QL, 64), 256>>>(S, BD, diffb, ef, Ph);
    pv_mma<<<dim3(8, 64), 256, PV_SMEM>>>(Ph, vth, at);
    vmean_fix<<<32, 64>>>(v, at);

    // back half
    gemm_mma<0,0><<<dim3(8,16,2), 256, GSMEM_BYTES>>>(at, woC, nullptr, o, nullptr,
        (size_t)M2*DM, (size_t)M2*DM, QL, DM, DM);
    add_ln<1><<<2*M2, 256>>>(o, h, g, lnga, lnba, y, yh);
    gemm_mma<2,1><<<dim3(32,16,2), 256, GSMEM_BYTES>>>(yh, w1T, b1, nullptr, th,
        (size_t)M2*DM, (size_t)M2*DI, QL, DM, DI);
    gemm_mma<1,0><<<dim3(8,16,2), 256, GSMEM_BYTES>>>(th, w2T, b2, z, nullptr,
        (size_t)M2*DI, (size_t)M2*DM, QL, DI, DM);
    add_ln<0><<<2*M2, 256>>>(z, y, y + (size_t)M2*DM, lngf, lnbf, (float*)d_out, nullptr);
}

// round 16
// speedup vs baseline: 1.0520x; 1.0183x over previous
#include <cuda_runtime.h>
#include <cuda_fp16.h>
#include <math.h>
#include <stdint.h>

#define QL 1024
#define NH 16
#define DH 64
#define DM 1024
#define DI 4096
#define RL 2048
#define M2 (QL*2)
#define MR (RL*2)
#define ATT_SCALE 0.125f
#define SSTR ((size_t)32*QL*QL)
#define BSTR ((size_t)32*QL*RL)

__device__ __forceinline__ uint32_t smem_u32(const void* p) {
    uint32_t a;
    asm("{ .reg .u64 t; cvta.to.shared.u64 t, %1; cvt.u32.u64 %0, t; }" : "=r"(a) : "l"(p));
    return a;
}
__device__ __forceinline__ void cp16(uint32_t dst, const void* src) {
    asm volatile("cp.async.cg.shared.global [%0], [%1], 16;" :: "r"(dst), "l"(src));
}
__device__ __forceinline__ void cp_commit() { asm volatile("cp.async.commit_group;" ::: "memory"); }
__device__ __forceinline__ void ldsm4(uint32_t (&r)[4], uint32_t addr) {
    asm volatile("ldmatrix.sync.aligned.m8n8.x4.shared.b16 {%0,%1,%2,%3}, [%4];"
        : "=r"(r[0]), "=r"(r[1]), "=r"(r[2]), "=r"(r[3]) : "r"(addr));
}
__device__ __forceinline__ void mma16816(float (&d)[4], const uint32_t (&a)[4],
                                         uint32_t b0, uint32_t b1) {
    asm volatile("mma.sync.aligned.m16n8k16.row.col.f32.f16.f16.f32 "
        "{%0,%1,%2,%3},{%4,%5,%6,%7},{%8,%9},{%0,%1,%2,%3};"
        : "+f"(d[0]), "+f"(d[1]), "+f"(d[2]), "+f"(d[3])
        : "r"(a[0]), "r"(a[1]), "r"(a[2]), "r"(a[3]), "r"(b0), "r"(b1));
}

// ---------------- scratch ----------------
__device__ float g_v [M2*DM];
__device__ float g_ef[2*M2*NH*2];
__device__ float g_o [2*M2*DM];
__device__ float g_y [2*M2*DM];
__device__ float g_z [2*M2*DM];
__device__ float g_bkT [32*QL];
__device__ float g_bkrT[32*RL];
__device__ __align__(256) __half g_S [2*SSTR];     // fp16 score storage
__device__ __align__(256) __half g_BD[2*BSTR];     // fp16 bd storage
__device__ __align__(256) __half g_diffb[(size_t)2*QL*QL];
__device__ __align__(256) __half g_hb[M2*DM], g_rb[MR*DM], g_gb[M2*DM];
__device__ __align__(256) __half g_wqT[DM*DM], g_wkT[DM*DM], g_wvT[DM*DM];
__device__ __align__(256) __half g_wrT[DM*DM], g_woC[DM*DM];
__device__ __align__(256) __half g_w1T[DM*DI], g_w2T[DI*DM];
__device__ __align__(256) __half g_q1h[32*QL*DH], g_q2h[32*QL*DH];
__device__ __align__(256) __half g_khh[32*QL*DH];
__device__ __align__(256) __half g_krh[32*RL*DH];
__device__ __align__(256) __half g_vth[32*DH*QL];
__device__ __align__(256) __half g_Ph [2*SSTR];
__device__ __align__(256) __half g_at [2*M2*DM];
__device__ __align__(256) __half g_yh [2*M2*DM];
__device__ __align__(256) __half g_th [2*M2*DI];

// ---------------- small kernels ----------------
__global__ void conv_hg(const float* __restrict__ H, const float* __restrict__ G,
                        __half* __restrict__ HB, __half* __restrict__ GB, int n4)
{
    int i = blockIdx.x * blockDim.x + threadIdx.x;
    if (i >= n4) return;
    const float* X = blockIdx.y ? G : H;
    __half* out = blockIdx.y ? GB : HB;
    float4 v = ((const float4*)X)[i];
    ((__half2*)out)[2*i]   = __halves2half2(__float2half_rn(v.x), __float2half_rn(v.y));
    ((__half2*)out)[2*i+1] = __halves2half2(__float2half_rn(v.z), __float2half_rn(v.w));
}

__global__ void conv_half(const float* __restrict__ X, __half* __restrict__ out, int n4)
{
    int i = blockIdx.x * blockDim.x + threadIdx.x;
    if (i >= n4) return;
    float4 v = ((const float4*)X)[i];
    ((__half2*)out)[2*i]   = __halves2half2(__float2half_rn(v.x), __float2half_rn(v.y));
    ((__half2*)out)[2*i+1] = __halves2half2(__float2half_rn(v.z), __float2half_rn(v.w));
}

__global__ void convT4_half(const float* __restrict__ W0, const float* __restrict__ W1,
                            const float* __restrict__ W2, const float* __restrict__ W3,
                            __half* __restrict__ O0, __half* __restrict__ O1,
                            __half* __restrict__ O2, __half* __restrict__ O3)
{
    __shared__ float t[32][33];
    const float* W = (blockIdx.z == 0) ? W0 : (blockIdx.z == 1) ? W1 : (blockIdx.z == 2) ? W2 : W3;
    __half* out    = (blockIdx.z == 0) ? O0 : (blockIdx.z == 1) ? O1 : (blockIdx.z == 2) ? O2 : O3;
    int k0 = blockIdx.y * 32, n0 = blockIdx.x * 32;
    int tx = threadIdx.x, ty = threadIdx.y;
#pragma unroll
    for (int p = 0; p < 4; p++)
        t[ty + p*8][tx] = W[(size_t)(k0 + ty + p*8)*DM + n0 + tx];
    __syncthreads();
#pragma unroll
    for (int p = 0; p < 4; p++)
        out[(size_t)(n0 + ty + p*8)*DM + k0 + tx] = __float2half_rn(t[tx][ty + p*8]);
}

__global__ void convT_half(const float* __restrict__ W, __half* __restrict__ out, int K, int N)
{
    __shared__ float t[32][33];
    int k0 = blockIdx.y * 32, n0 = blockIdx.x * 32;
    int tx = threadIdx.x, ty = threadIdx.y;
#pragma unroll
    for (int p = 0; p < 4; p++)
        t[ty + p*8][tx] = W[(size_t)(k0 + ty + p*8)*N + n0 + tx];
    __syncthreads();
#pragma unroll
    for (int p = 0; p < 4; p++)
        out[(size_t)(n0 + ty + p*8)*K + k0 + tx] = __float2half_rn(t[tx][ty + p*8]);
}

__global__ void repack_vT(const float* __restrict__ V, __half* __restrict__ out)
{
    __shared__ float tile[32][33];
    int j0 = blockIdx.x * 32, d0 = blockIdx.y * 32;
    int bn = blockIdx.z, b = bn >> 4, n = bn & 15;
    int tx = threadIdx.x, ty = threadIdx.y;
#pragma unroll
    for (int p = 0; p < 4; p++)
        tile[ty + p*8][tx] = V[((size_t)(j0 + ty + p*8)*2 + b)*DM + n*DH + d0 + tx];
    __syncthreads();
#pragma unroll
    for (int p = 0; p < 4; p++)
        out[((size_t)bn*DH + d0 + ty + p*8)*QL + j0 + tx] = __float2half_rn(tile[tx][ty + p*8]);
}

__global__ void prep_diff(const float* __restrict__ seg_mat, __half* __restrict__ diff)
{
    size_t idx = (size_t)blockIdx.x * blockDim.x + threadIdx.x;
    if (idx >= (size_t)2*QL*QL) return;
    int j = idx & 1023, i = (idx >> 10) & 1023, b = (int)(idx >> 20);
    diff[idx] = __float2half_rn(seg_mat[(((size_t)i*QL + j)*2 + b)*2 + 1]);
}

__global__ void bias_dotT_h(const __half* __restrict__ X, const float* __restrict__ bias,
                            float* __restrict__ outT, int total)
{
    const int gw = (blockIdx.x * blockDim.x + threadIdx.x) >> 5;
    const int lane = threadIdx.x & 31;
    if (gw >= total) return;
    const int rows = total >> 5;
    const int bn = gw / rows;
    const int nn = bn & 15;
    float s = bias[nn*DH + lane]      * __half2float(X[(size_t)gw*DH + lane])
            + bias[nn*DH + 32 + lane] * __half2float(X[(size_t)gw*DH + 32 + lane]);
#pragma unroll
    for (int o = 16; o; o >>= 1) s += __shfl_xor_sync(0xffffffffu, s, o);
    if (!lane) outT[gw] = s;
}

__global__ void ef_kernel_h(const __half* __restrict__ Q1, const __half* __restrict__ Q2,
                            const float* __restrict__ rsb, const float* __restrict__ se)
{
    const int gw = (blockIdx.x * blockDim.x + threadIdx.x) >> 5;
    const int lane = threadIdx.x & 31;
    if (gw >= M2 * NH) return;
    const __half* qh = blockIdx.y ? Q2 : Q1;
    float* ef = g_ef + (size_t)blockIdx.y * M2 * NH * 2;
    const int i = gw >> 5, b = (gw >> 4) & 1, n = gw & 15;
    const size_t qb = ((size_t)(b*16 + n)*QL + i)*DH;
    const float v0 = __half2float(qh[qb + lane])      + rsb[n*DH + lane];
    const float v1 = __half2float(qh[qb + 32 + lane]) + rsb[n*DH + 32 + lane];
    float s0 = v0*se[n*DH + lane] + v1*se[n*DH + 32 + lane];
    float s1 = v0*se[NH*DH + n*DH + lane] + v1*se[NH*DH + n*DH + 32 + lane];
#pragma unroll
    for (int o = 16; o; o >>= 1) {
        s0 += __shfl_xor_sync(0xffffffffu, s0, o);
        s1 += __shfl_xor_sync(0xffffffffu, s1, o);
    }
    if (!lane) { ef[gw*2] = s0; ef[gw*2 + 1] = s1; }
}

__global__ void vmean_fix(const float* __restrict__ V, __half* __restrict__ O)
{
    int bn = blockIdx.x, b = bn >> 4, n = bn & 15;
    int d = threadIdx.x;
    float s = 0.f;
    for (int j = 0; j < QL; j++) s += V[((size_t)j*2 + b)*DM + n*DH + d];
    s *= (1.0f/1024.0f);
    O[(size_t)M2*DM + (size_t)b*DM + n*DH + d] = __float2half_rn(s);
}

// ---------------- dense GEMM: 1-pass fp16, 3-stage, 2 CTA/SM ----------------
#define GSTAGE 32768
#define GSMEM_BYTES (3*GSTAGE)

__device__ __forceinline__ void g_load_stage(
    const __half* __restrict__ A, const __half* __restrict__ B,
    uint32_t st, int m0, int n0, int K, int kc, int tid)
{
    const size_t ko = (size_t)kc * 64;
#pragma unroll
    for (int p = 0; p < 4; p++) {
        int c = p*256 + tid;
        int row = c >> 3, kcol = c & 7;
        uint32_t sw = (uint32_t)(row*128 + kcol*16) ^ ((row & 7) << 4);
        cp16(st + sw,         A + (size_t)(m0 + row)*K + ko + kcol*8);
        cp16(st + 16384 + sw, B + (size_t)(n0 + row)*K + ko + kcol*8);
    }
    cp_commit();
}

// OUT: 0 fp32 C; 1 fp16 row-major; 3 fp32 C + head-major fp16; 4 head-major fp16 only
template<int EPI, int OUT>
__device__ __forceinline__ void gemm_core(
    const __half* __restrict__ A, const __half* __restrict__ B,
    const float* __restrict__ bias, float* __restrict__ C,
    __half* __restrict__ Ch, int rowsPerB, int K, int ldc)
{
    extern __shared__ char dsm[];
    const uint32_t sbase = smem_u32(dsm);
    const int tid = threadIdx.x, lane = tid & 31, warp = tid >> 5;
    const int m0 = blockIdx.y * 128, n0 = blockIdx.x * 128;
    const int wm = (warp & 1) * 64, wn = (warp >> 1) * 32;
    const int NC = K >> 6;

    float acc[4][4][4] = {};
    g_load_stage(A, B, sbase,            m0, n0, K, 0, tid);
    g_load_stage(A, B, sbase + GSTAGE,   m0, n0, K, 1, tid);
    g_load_stage(A, B, sbase + 2*GSTAGE, m0, n0, K, 2, tid);
    asm volatile("cp.async.wait_group 2;" ::: "memory");
    __syncthreads();

    const int arow = wm + (lane & 15), akb = lane & 16;
    const int brow = wn + ((lane & 16) >> 1) + (lane & 7), bkb = (lane & 8) << 1;

    int buf = 0;
    for (int kc = 0; kc < NC; kc++) {
        const uint32_t st = sbase + buf * GSTAGE;
#pragma unroll
        for (int ks = 0; ks < 4; ks++) {
            const int kb = ks*32;
            uint32_t ah[4][4], bh[2][4];
#pragma unroll
            for (int im = 0; im < 4; im++) {
                int row = arow + im*16;
                uint32_t off = (uint32_t)(row*128 + kb + akb) ^ ((row & 7) << 4);
                ldsm4(ah[im], st + off);
            }
#pragma unroll
            for (int np = 0; np < 2; np++) {
                int row = brow + np*16;
                uint32_t off = (uint32_t)(row*128 + kb + bkb) ^ ((row & 7) << 4);
                ldsm4(bh[np], st + 16384 + off);
            }
#pragma unroll
            for (int im = 0; im < 4; im++)
#pragma unroll
                for (int in = 0; in < 4; in++) {
                    const int np = in >> 1, hf = (in & 1) * 2;
                    mma16816(acc[im][in], ah[im], bh[np][hf], bh[np][hf+1]);
                }
        }
        __syncthreads();
        if (kc + 3 < NC) {
            g_load_stage(A, B, sbase + buf*GSTAGE, m0, n0, K, kc + 3, tid);
            asm volatile("cp.async.wait_group 2;" ::: "memory");
        } else if (kc + 2 < NC) {
            asm volatile("cp.async.wait_group 1;" ::: "memory");
        } else {
            asm volatile("cp.async.wait_group 0;" ::: "memory");
        }
        __syncthreads();
        buf++; if (buf == 3) buf = 0;
    }

    const int rbase = m0 + wm + (lane >> 2);
    const int cbase = n0 + wn + 2*(lane & 3);
#pragma unroll
    for (int im = 0; im < 4; im++) {
#pragma unroll
        for (int in = 0; in < 4; in++) {
            int col = cbase + in*8;
            float v0 = acc[im][in][0], v1 = acc[im][in][1];
            float v2 = acc[im][in][2], v3 = acc[im][in][3];
            if (EPI >= 1) {
                float b0 = bias[col], b1 = bias[col+1];
                v0 += b0; v1 += b1; v2 += b0; v3 += b1;
            }
            if (EPI == 2) {
                v0 = 0.5f*v0*(1.0f + erff(v0*0.7071067811865476f));
                v1 = 0.5f*v1*(1.0f + erff(v1*0.7071067811865476f));
                v2 = 0.5f*v2*(1.0f + erff(v2*0.7071067811865476f));
                v3 = 0.5f*v3*(1.0f + erff(v3*0.7071067811865476f));
            }
            int r0 = rbase + im*16, r1 = r0 + 8;
            if (OUT == 0 || OUT == 3) {
                *(float2*)(C + (size_t)r0*ldc + col) = make_float2(v0, v1);
                *(float2*)(C + (size_t)r1*ldc + col) = make_float2(v2, v3);
            }
            if (OUT == 1) {
                *(__half2*)(Ch + (size_t)r0*ldc + col) =
                    __halves2half2(__float2half_rn(v0), __float2half_rn(v1));
                *(__half2*)(Ch + (size_t)r1*ldc + col) =
                    __halves2half2(__float2half_rn(v2), __float2half_rn(v3));
            }
            if (OUT >= 3) {
                int nh = col >> 6, d = col & 63;
                size_t d0 = (((size_t)(r0 & 1)*NH + nh)*rowsPerB + (r0 >> 1))*DH + d;
                size_t d1 = (((size_t)(r1 & 1)*NH + nh)*rowsPerB + (r1 >> 1))*DH + d;
                *(__half2*)(Ch + d0) = __halves2half2(__float2half_rn(v0), __float2half_rn(v1));
                *(__half2*)(Ch + d1) = __halves2half2(__float2half_rn(v2), __float2half_rn(v3));
            }
        }
    }
}

template<int EPI, int OUT>
__global__ void __launch_bounds__(256, 2) gemm_mma(
    const __half* __restrict__ A, const __half* __restrict__ B,
    const float* __restrict__ bias, float* __restrict__ C, __half* __restrict__ Ch,
    size_t zsA, size_t zsC, int rowsPerB, int K, int ldc)
{
    const size_t zo = blockIdx.z;
    gemm_core<EPI, OUT>(A + zo*zsA, B, bias,
                        (OUT == 0 || OUT == 3) ? C + zo*zsC : C,
                        (OUT >= 1) ? Ch + zo*zsC : Ch,
                        rowsPerB, K, ldc);
}

__global__ void __launch_bounds__(256, 2) projHKV()
{
    switch (blockIdx.z) {
    case 0: gemm_core<0,4>(g_hb, g_wkT, nullptr, nullptr, g_khh, QL, DM, DM); break;
    case 1: gemm_core<0,0>(g_hb, g_wvT, nullptr, g_v, nullptr, QL, DM, DM); break;
    default: gemm_core<0,4>(g_hb, g_wqT, nullptr, nullptr, g_q1h, QL, DM, DM); break;
    }
}

// ---------------- batched score GEMM (1-pass), causal-pruned, fp16 output ----------------
#define SC_SMEM 32768

__global__ void __launch_bounds__(256, 2) score_mma(
    const __half* __restrict__ Q1, const __half* __restrict__ Q2,
    const __half* __restrict__ Km, const float* __restrict__ biasT,
    __half* __restrict__ C, size_t zsC, int Ncols, int window)
{
    extern __shared__ char dsm[];
    const uint32_t st = smem_u32(dsm);
    const int tid = threadIdx.x, lane = tid & 31, warp = tid >> 5;
    const int zz = blockIdx.z, s = zz >> 5, bn = zz & 31;
    const __half* Q = s ? Q2 : Q1;
    C += (size_t)s * zsC;

    int i0, j0;
    if (!window) {
        int t = blockIdx.x;
        int it = (int)((sqrtf(8.f*t + 1.f) - 1.f) * 0.5f);
        if ((it + 1)*(it + 2)/2 <= t) it++;
        else if (it*(it + 1)/2 > t) it--;
        int jt = t - it*(it + 1)/2;
        i0 = it * 128; j0 = jt * 128;
    } else {
        int it = blockIdx.y;
        int bx = blockIdx.x;
        if (bx > it + 1) return;
        i0 = it * 128;
        j0 = (7 - it + bx) * 128;
    }

    const size_t qb = ((size_t)bn*QL + i0)*DH;
    const size_t kb = ((size_t)bn*Ncols + j0)*DH;
#pragma unroll
    for (int p = 0; p < 4; p++) {
        int c = p*256 + tid;
        int row = c >> 3, kcol = c & 7;
        uint32_t sw = (uint32_t)(row*128 + kcol*16) ^ ((row & 7) << 4);
        cp16(st + sw,         Q  + qb + (size_t)row*DH + kcol*8);
        cp16(st + 16384 + sw, Km + kb + (size_t)row*DH + kcol*8);
    }
    cp_commit();
    asm volatile("cp.async.wait_group 0;" ::: "memory");
    __syncthreads();

    const int wm = (warp & 1) * 64, wn = (warp >> 1) * 32;
    const int arow = wm + (lane & 15), akb = lane & 16;
    const int brow = wn + ((lane & 16) >> 1) + (lane & 7), bkb = (lane & 8) << 1;

    float acc[4][4][4] = {};
#pragma unroll
    for (int ks = 0; ks < 4; ks++) {
        const int kbyte = ks*32;
        uint32_t ah[4][4], bh[2][4];
#pragma unroll
        for (int im = 0; im < 4; im++) {
            int row = arow + im*16;
            uint32_t off = (uint32_t)(row*128 + kbyte + akb) ^ ((row & 7) << 4);
            ldsm4(ah[im], st + off);
        }
#pragma unroll
        for (int np = 0; np < 2; np++) {
            int row = brow + np*16;
            uint32_t off = (uint32_t)(row*128 + kbyte + bkb) ^ ((row & 7) << 4);
            ldsm4(bh[np], st + 16384 + off);
        }
#pragma unroll
        for (int im = 0; im < 4; im++)
#pragma unroll
            for (int in = 0; in < 4; in++) {
                const int np = in >> 1, hf = (in & 1) * 2;
                mma16816(acc[im][in], ah[im], bh[np][hf], bh[np][hf+1]);
            }
    }

    __half* Cb = C + (size_t)bn*QL*Ncols;
    const float* bt = biasT + (size_t)bn*Ncols;
    const int rbase = i0 + wm + (lane >> 2);
    const int cbase = j0 + wn + 2*(lane & 3);
#pragma unroll
    for (int im = 0; im < 4; im++)
#pragma unroll
        for (int in = 0; in < 4; in++) {
            int col = cbase + in*8;
            float b0 = bt[col], b1 = bt[col+1];
            int r0 = rbase + im*16, r1 = r0 + 8;
            *(__half2*)(Cb + (size_t)r0*Ncols + col) = __halves2half2(
                __float2half_rn(acc[im][in][0] + b0), __float2half_rn(acc[im][in][1] + b1));
            *(__half2*)(Cb + (size_t)r1*Ncols + col) = __halves2half2(
                __float2half_rn(acc[im][in][2] + b0), __float2half_rn(acc[im][in][3] + b1));
        }
}

// ---------------- fused combine + softmax + fp16 P ----------------
__global__ void __launch_bounds__(256) softmax_fused(
    const __half* __restrict__ S, const __half* __restrict__ BD,
    const __half* __restrict__ diff, const float* __restrict__ ef,
    __half* __restrict__ Ph)
{
    __shared__ float red[8];
    const int i = blockIdx.x;
    const int zz = blockIdx.y, s = zz >> 5, bn = zz & 31, b = bn >> 4, n = bn & 15;
    const int jmax = ((i >> 7) + 1) << 7;
    const __half* Sr = S  + (size_t)s*SSTR + ((size_t)bn << 20) + ((size_t)i << 10);
    const __half* Br = BD + (size_t)s*BSTR + ((size_t)bn << 21) + ((size_t)i << 11) + (QL - i);
    const __half* Dr = diff + ((size_t)b << 20) + ((size_t)i << 10);
    const float* efs = ef + (size_t)s*M2*NH*2;
    const float e0 = efs[(((size_t)i*2 + b)*NH + n)*2];
    const float de = efs[(((size_t)i*2 + b)*NH + n)*2 + 1] - e0;
    const int t = threadIdx.x, lane = t & 31, w = t >> 5;

    float v[4];
#pragma unroll
    for (int p = 0; p < 4; p++) {
        int j = t + p*256;
        if (j < jmax) {
            float sc = (__half2float(Sr[j]) + __half2float(Br[j])
                        + e0 + de*__half2float(Dr[j])) * ATT_SCALE;
            bool blocked = s ? (j >= i) : (j > i);
            v[p] = blocked ? sc - 1e30f : sc;
        } else v[p] = -1e30f;
    }
    float m = fmaxf(fmaxf(v[0], v[1]), fmaxf(v[2], v[3]));
#pragma unroll
    for (int o = 16; o; o >>= 1) m = fmaxf(m, __shfl_xor_sync(0xffffffffu, m, o));
    if (!lane) red[w] = m;
    __syncthreads();
    m = red[lane & 7];
#pragma unroll
    for (int o = 4; o; o >>= 1) m = fmaxf(m, __shfl_xor_sync(0xffffffffu, m, o));
    float sum = 0.f;
#pragma unroll
    for (int p = 0; p < 4; p++) { v[p] = expf(v[p] - m); sum += v[p]; }
#pragma unroll
    for (int o = 16; o; o >>= 1) sum += __shfl_xor_sync(0xffffffffu, sum, o);
    __syncthreads();
    if (!lane) red[w] = sum;
    __syncthreads();
    sum = red[lane & 7];
#pragma unroll
    for (int o = 4; o; o >>= 1) sum += __shfl_xor_sync(0xffffffffu, sum, o);
    const float inv = 1.0f / sum;
    const size_t base = (size_t)s*SSTR + ((size_t)bn << 20) + ((size_t)i << 10);
#pragma unroll
    for (int p = 0; p < 4; p++) {
        int j = t + p*256;
        if (j < jmax) Ph[base + j] = __float2half_rn(v[p] * inv);
    }
}

// ---------------- batched PV GEMM (1-pass, causal K) ----------------
#define PV_STAGE 24576
#define PV_SMEM (2*PV_STAGE)

__device__ __forceinline__ void pv_load(
    const __half* __restrict__ P, const __half* __restrict__ V,
    uint32_t st, size_t pbase, size_t vbase, int kc, int tid)
{
    const size_t ko = (size_t)kc * 64;
#pragma unroll
    for (int p = 0; p < 4; p++) {
        int c = p*256 + tid;
        int row = c >> 3, kcol = c & 7;
        uint32_t sw = (uint32_t)(row*128 + kcol*16) ^ ((row & 7) << 4);
        cp16(st + sw, P + pbase + (size_t)row*QL + ko + kcol*8);
    }
#pragma unroll
    for (int p = 0; p < 2; p++) {
        int c = p*256 + tid;
        int row = c >> 3, kcol = c & 7;
        uint32_t sw = (uint32_t)(row*128 + kcol*16) ^ ((row & 7) << 4);
        cp16(st + 16384 + sw, V + vbase + (size_t)row*QL + ko + kcol*8);
    }
    cp_commit();
}

__global__ void __launch_bounds__(256, 2) pv_mma(
    const __half* __restrict__ P, const __half* __restrict__ V, __half* __restrict__ O)
{
    extern __shared__ char dsm[];
    const uint32_t sbase = smem_u32(dsm);
    const int tid = threadIdx.x, lane = tid & 31, warp = tid >> 5;
    const int zz = blockIdx.y, s = zz >> 5, bn = zz & 31, b = bn >> 4, n = bn & 15;
    const int it = blockIdx.x;
    const int i0 = it * 128;
    const int NC = 2*it + 2;
    const size_t pbase = (size_t)s*SSTR + ((size_t)bn << 20) + (size_t)i0*QL;
    const size_t vbase = (size_t)bn * DH * QL;
    const size_t obase = (size_t)s * M2 * DM;

    float acc[2][4][4] = {};
    pv_load(P, V, sbase,            pbase, vbase, 0, tid);
    pv_load(P, V, sbase + PV_STAGE, pbase, vbase, 1, tid);
    asm volatile("cp.async.wait_group 1;" ::: "memory");
    __syncthreads();

    const int wm = (warp & 3) * 32, wn = (warp >> 2) * 32;
    const int arow = wm + (lane & 15), akb = lane & 16;
    const int brow = wn + ((lane & 16) >> 1) + (lane & 7), bkb = (lane & 8) << 1;

    for (int kc = 0; kc < NC; kc++) {
        const uint32_t st = sbase + (kc & 1) * PV_STAGE;
#pragma unroll
        for (int ks = 0; ks < 4; ks++) {
            const int kb = ks*32;
            uint32_t ah[2][4], bh[2][4];
#pragma unroll
            for (int im = 0; im < 2; im++) {
                int row = arow + im*16;
                uint32_t off = (uint32_t)(row*128 + kb + akb) ^ ((row & 7) << 4);
                ldsm4(ah[im], st + off);
            }
#pragma unroll
            for (int np = 0; np < 2; np++) {
                int row = brow + np*16;
                uint32_t off = (uint32_t)(row*128 + kb + bkb) ^ ((row & 7) << 4);
                ldsm4(bh[np], st + 16384 + off);
            }
#pragma unroll
            for (int im = 0; im < 2; im++)
#pragma unroll
                for (int in = 0; in < 4; in++) {
                    const int np = in >> 1, hf = (in & 1) * 2;
                    mma16816(acc[im][in], ah[im], bh[np][hf], bh[np][hf+1]);
                }
        }
        __syncthreads();
        if (kc + 2 < NC) {
            pv_load(P, V, sbase + (kc & 1)*PV_STAGE, pbase, vbase, kc + 2, tid);
            asm volatile("cp.async.wait_group 1;" ::: "memory");
        } else {
            asm volatile("cp.async.wait_group 0;" ::: "memory");
        }
        __syncthreads();
    }

    const int rl = wm + (lane >> 2);
    const int cb = wn + 2*(lane & 3);
#pragma unroll
    for (int im = 0; im < 2; im++)
#pragma unroll
        for (int in = 0; in < 4; in++) {
            int col = cb + in*8;
            int r0 = i0 + rl + im*16, r1 = r0 + 8;
            *(__half2*)(O + obase + ((size_t)r0*2 + b)*DM + n*DH + col) =
                __halves2half2(__float2half_rn(acc[im][in][0]), __float2half_rn(acc[im][in][1]));
            *(__half2*)(O + obase + ((size_t)r1*2 + b)*DM + n*DH + col) =
                __halves2half2(__float2half_rn(acc[im][in][2]), __float2half_rn(acc[im][in][3]));
        }
}

// ---------------- residual + LayerNorm (merged streams) ----------------
template<int WB16>
__global__ void __launch_bounds__(256) add_ln(
    const float* __restrict__ a, const float* __restrict__ x0, const float* __restrict__ x1,
    const float* __restrict__ gamma, const float* __restrict__ beta,
    float* __restrict__ out, __half* __restrict__ oh)
{
    __shared__ float buf[1024];
    __shared__ float red[8];
    __shared__ float s_stat;
    const size_t base = (size_t)blockIdx.x << 10;
    const int str = blockIdx.x >> 11;
    const size_t lbase = (size_t)(blockIdx.x & 2047) << 10;
    const float* x = str ? x1 : x0;
    const int t = threadIdx.x, lane = t & 31, w = t >> 5;
    float sum = 0.f;
#pragma unroll
    for (int p = 0; p < 4; p++) {
        float v = a[base + t + p*256] + x[lbase + t + p*256];
        buf[t + p*256] = v; sum += v;
    }
#pragma unroll
    for (int o = 16; o; o >>= 1) sum += __shfl_xor_sync(0xffffffffu, sum, o);
    if (!lane) red[w] = sum;
    __syncthreads();
    if (t == 0) { float s = 0; for (int i = 0; i < 8; i++) s += red[i]; s_stat = s * (1.0f/1024.0f); }
    __syncthreads();
    const float mean = s_stat;
    float vs = 0.f;
#pragma unroll
    for (int p = 0; p < 4; p++) { float d = buf[t + p*256] - mean; vs += d*d; }
#pragma unroll
    for (int o = 16; o; o >>= 1) vs += __shfl_xor_sync(0xffffffffu, vs, o);
    __syncthreads();
    if (!lane) red[w] = vs;
    __syncthreads();
    if (t == 0) { float s = 0; for (int i = 0; i < 8; i++) s += red[i]; s_stat = s * (1.0f/1024.0f); }
    __syncthreads();
    const float r = rsqrtf(s_stat + 1e-12f);
#pragma unroll
    for (int p = 0; p < 4; p++) {
        int c = t + p*256;
        float val = (buf[c] - mean) * r * gamma[c] + beta[c];
        out[base + c] = val;
        if (WB16) oh[base + c] = __float2half_rn(val);
    }
}

// ---------------- host ----------------
extern "C" void kernel_launch(void* const* d_in, const int* in_sizes, int n_in,
                              void* d_out, int out_size)
{
    (void)in_sizes; (void)n_in; (void)out_size;
    const float* h       = (const float*)d_in[0];
    const float* g       = (const float*)d_in[1];
    const float* r       = (const float*)d_in[2];
    const float* seg_mat = (const float*)d_in[5];
    const float* wq      = (const float*)d_in[6];
    const float* wk      = (const float*)d_in[7];
    const float* wv      = (const float*)d_in[8];
    const float* wo      = (const float*)d_in[9];
    const float* wr      = (const float*)d_in[10];
    const float* rwb     = (const float*)d_in[11];
    const float* rrb     = (const float*)d_in[12];
    const float* rsb     = (const float*)d_in[13];
    const float* se      = (const float*)d_in[14];
    const float* lnga    = (const float*)d_in[15];
    const float* lnba    = (const float*)d_in[16];
    const float* w1      = (const float*)d_in[17];
    const float* b1      = (const float*)d_in[18];
    const float* w2      = (const float*)d_in[19];
    const float* b2      = (const float*)d_in[20];
    const float* lngf    = (const float*)d_in[21];
    const float* lnbf    = (const float*)d_in[22];

    cudaFuncSetAttribute(projHKV,       cudaFuncAttributeMaxDynamicSharedMemorySize, GSMEM_BYTES);
    cudaFuncSetAttribute(gemm_mma<0,0>, cudaFuncAttributeMaxDynamicSharedMemorySize, GSMEM_BYTES);
    cudaFuncSetAttribute(gemm_mma<0,4>, cudaFuncAttributeMaxDynamicSharedMemorySize, GSMEM_BYTES);
    cudaFuncSetAttribute(gemm_mma<2,1>, cudaFuncAttributeMaxDynamicSharedMemorySize, GSMEM_BYTES);
    cudaFuncSetAttribute(gemm_mma<1,0>, cudaFuncAttributeMaxDynamicSharedMemorySize, GSMEM_BYTES);
    cudaFuncSetAttribute(score_mma,     cudaFuncAttributeMaxDynamicSharedMemorySize, SC_SMEM);
    cudaFuncSetAttribute(pv_mma,        cudaFuncAttributeMaxDynamicSharedMemorySize, PV_SMEM);

    float *v,*ef,*o,*y,*z,*bkT,*bkrT;
    __half *S,*BD,*hb,*rb,*gb,*wqT,*wkT,*wvT,*wrT,*woC,*w1T,*w2T,*diffb;
    __half *q1h,*q2h,*khh,*krh,*vth,*Ph,*at,*yh,*th;
    cudaGetSymbolAddress((void**)&v,    g_v);
    cudaGetSymbolAddress((void**)&ef,   g_ef);
    cudaGetSymbolAddress((void**)&o,    g_o);
    cudaGetSymbolAddress((void**)&y,    g_y);
    cudaGetSymbolAddress((void**)&z,    g_z);
    cudaGetSymbolAddress((void**)&bkT,  g_bkT);
    cudaGetSymbolAddress((void**)&bkrT, g_bkrT);
    cudaGetSymbolAddress((void**)&S,    g_S);
    cudaGetSymbolAddress((void**)&BD,   g_BD);
    cudaGetSymbolAddress((void**)&diffb,g_diffb);
    cudaGetSymbolAddress((void**)&hb,   g_hb);
    cudaGetSymbolAddress((void**)&rb,   g_rb);
    cudaGetSymbolAddress((void**)&gb,   g_gb);
    cudaGetSymbolAddress((void**)&wqT,  g_wqT);
    cudaGetSymbolAddress((void**)&wkT,  g_wkT);
    cudaGetSymbolAddress((void**)&wvT,  g_wvT);
    cudaGetSymbolAddress((void**)&wrT,  g_wrT);
    cudaGetSymbolAddress((void**)&woC,  g_woC);
    cudaGetSymbolAddress((void**)&w1T,  g_w1T);
    cudaGetSymbolAddress((void**)&w2T,  g_w2T);
    cudaGetSymbolAddress((void**)&q1h,  g_q1h);
    cudaGetSymbolAddress((void**)&q2h,  g_q2h);
    cudaGetSymbolAddress((void**)&khh,  g_khh);
    cudaGetSymbolAddress((void**)&krh,  g_krh);
    cudaGetSymbolAddress((void**)&vth,  g_vth);
    cudaGetSymbolAddress((void**)&Ph,   g_Ph);
    cudaGetSymbolAddress((void**)&at,   g_at);
    cudaGetSymbolAddress((void**)&yh,   g_yh);
    cudaGetSymbolAddress((void**)&th,   g_th);

    dim3 tb(32, 8);
    convT4_half<<<dim3(DM/32, DM/32, 4), tb>>>(wk, wv, wq, wr, wkT, wvT, wqT, wrT);
    conv_hg<<<dim3((M2*DM/4 + 255)/256, 2), 256>>>(h, g, hb, gb, M2*DM/4);
    conv_half<<<(MR*DM/4 + 255)/256, 256>>>(r, rb, MR*DM/4);
    conv_half<<<(DM*DM/4 + 255)/256, 256>>>(wo, woC, DM*DM/4);
    projHKV<<<dim3(8, 16, 3), 256, GSMEM_BYTES>>>();

    convT_half<<<dim3(DI/32, DM/32), tb>>>(w1, w1T, DM, DI);
    convT_half<<<dim3(DM/32, DI/32), tb>>>(w2, w2T, DI, DM);
    prep_diff<<<(2*QL*QL + 255)/256, 256>>>(seg_mat, diffb);

    gemm_mma<0,4><<<dim3(8,32,1), 256, GSMEM_BYTES>>>(rb, wrT, nullptr, nullptr, krh, 0, 0, RL, DM, DM);
    gemm_mma<0,4><<<dim3(8,16,1), 256, GSMEM_BYTES>>>(gb, wqT, nullptr, nullptr, q2h, 0, 0, QL, DM, DM);
    repack_vT<<<dim3(QL/32, DH/32, 32), tb>>>(v, vth);

    bias_dotT_h<<<(32*QL*32 + 255)/256, 256>>>(khh, rwb, bkT,  32*QL);
    bias_dotT_h<<<(32*RL*32 + 255)/256, 256>>>(krh, rrb, bkrT, 32*RL);
    ef_kernel_h<<<dim3((M2*NH*32 + 255)/256, 2), 256>>>(q1h, q2h, rsb, se);

    // attention (split ac + windowed bd, causal-pruned, 1-pass fp16, fp16 score storage)
    score_mma<<<dim3(36, 1, 64), 256, SC_SMEM>>>(q1h, q2h, khh, bkT,  S,  SSTR, QL, 0);
    score_mma<<<dim3(9, 8, 64), 256, SC_SMEM>>>(q1h, q2h, krh, bkrT, BD, BSTR, RL, 1);
    softmax_fused<<<dim3(QL, 64), 256>>>(S, BD, diffb, ef, Ph);
    pv_mma<<<dim3(8, 64), 256, PV_SMEM>>>(Ph, vth, at);
    vmean_fix<<<32, 64>>>(v, at);

    // back half
    gemm_mma<0,0><<<dim3(8,16,2), 256, GSMEM_BYTES>>>(at, woC, nullptr, o, nullptr,
        (size_t)M2*DM, (size_t)M2*DM, QL, DM, DM);
    add_ln<1><<<2*M2, 256>>>(o, h, g, lnga, lnba, y, yh);
    gemm_mma<2,1><<<dim3(32,16,2), 256, GSMEM_BYTES>>>(yh, w1T, b1, nullptr, th,
        (size_t)M2*DM, (size_t)M2*DI, QL, DM, DI);
    gemm_mma<1,0><<<dim3(8,16,2), 256, GSMEM_BYTES>>>(th, w2T, b2, z, nullptr,
        (size_t)M2*DI, (size_t)M2*DM, QL, DI, DM);
    add_ln<0><<<2*M2, 256>>>(z, y, y + (size_t)M2*DM, lngf, lnbf, (float*)d_out, nullptr);
}